// round 2
// baseline (speedup 1.0000x reference)
#include <cuda_runtime.h>
#include <math.h>

#define BB 4
#define LL 2048
#define SS 2048
#define HH 8
#define EE 64
#define HE 512          // HH*EE
#define BH 32           // BB*HH
#define NELEM (BB*LL*HH*EE)   // 4194304
#define EPSF 1e-6f
#define SCALEF 0.125f   // 1/sqrt(64)

// -------- device scratch (alloc-free rule: __device__ globals) --------
__device__ float g_qt[NELEM];
__device__ float g_kt[NELEM];
__device__ float g_scores[(size_t)BH * LL * SS];   // 512 MB

// ==================== kernel 1: transform with per-(b,l,e) std over HEADS ====================
// std = jnp.std(x, axis=-2, ddof=1)  -> axis=-2 of [B,L,H,E] is H (8 heads)
__global__ void __launch_bounds__(512) k_transform(const float* __restrict__ q,
                                                   const float* __restrict__ k,
                                                   const float* __restrict__ dw,
                                                   const float* __restrict__ dp) {
    int sel = blockIdx.y;
    const float* x = (sel ? k : q) + (size_t)blockIdx.x * HE;
    float* o = (sel ? g_kt : g_qt) + (size_t)blockIdx.x * HE;
    float w = dw[0];
    float p = dp[0];
    int tid = threadIdx.x;          // 0..511 = h*64 + e
    int e = tid & 63;
    float v = x[tid];

    __shared__ float s1[512];
    __shared__ float istd[64];
    s1[tid] = v;
    __syncthreads();
    if (tid < 64) {
        float s = 0.f, ss = 0.f;
        #pragma unroll
        for (int h = 0; h < 8; h++) {
            float u = s1[h * 64 + tid];
            s += u; ss += u * u;
        }
        float mean = s * 0.125f;
        float var = (ss - s * mean) * (1.0f / 7.0f);    // unbiased, n=8
        istd[tid] = 1.0f / (sqrtf(fmaxf(var, 0.f)) + EPSF);
    }
    __syncthreads();
    o[tid] = tanhf(v * istd[e] * w) * p;
}

// ==================== kernel 2: scores = qt @ kt^T (per b,h) ====================
__global__ void __launch_bounds__(256) k_gemm_qk() {
    __shared__ float qs[64][65];   // [l_local][e]   (scalar broadcast reads)
    __shared__ float ks[64][68];   // [e][s_local]   (float4 reads)
    int bh = blockIdx.z;
    int l0 = blockIdx.y << 6;
    int s0 = blockIdx.x << 6;
    int tid = threadIdx.x;
    const float* Q = g_qt + (size_t)(bh >> 3) * LL * HE + (bh & 7) * EE;
    const float* K = g_kt + (size_t)(bh >> 3) * LL * HE + (bh & 7) * EE;

    {   // fill qs (natural layout, coalesced)
        int e = tid & 63, rg = tid >> 6;
        #pragma unroll
        for (int r = 0; r < 64; r += 4)
            qs[r + rg][e] = Q[(size_t)(l0 + r + rg) * HE + e];
    }
    {   // fill ks transposed [e][s]
        int e = tid & 63, sg = (tid >> 6) << 2;
        #pragma unroll
        for (int so = 0; so < 64; so += 16) {
            float a0 = K[(size_t)(s0 + so + sg + 0) * HE + e];
            float a1 = K[(size_t)(s0 + so + sg + 1) * HE + e];
            float a2 = K[(size_t)(s0 + so + sg + 2) * HE + e];
            float a3 = K[(size_t)(s0 + so + sg + 3) * HE + e];
            *(float4*)&ks[e][so + sg] = make_float4(a0, a1, a2, a3);
        }
    }
    __syncthreads();

    int tx = tid & 15, ty = tid >> 4;
    float acc[4][4] = {};
    #pragma unroll 8
    for (int kk = 0; kk < 64; kk++) {
        float a0 = qs[ty * 4 + 0][kk];
        float a1 = qs[ty * 4 + 1][kk];
        float a2 = qs[ty * 4 + 2][kk];
        float a3 = qs[ty * 4 + 3][kk];
        float4 bv = *(const float4*)&ks[kk][tx << 2];
        acc[0][0] += a0 * bv.x; acc[0][1] += a0 * bv.y; acc[0][2] += a0 * bv.z; acc[0][3] += a0 * bv.w;
        acc[1][0] += a1 * bv.x; acc[1][1] += a1 * bv.y; acc[1][2] += a1 * bv.z; acc[1][3] += a1 * bv.w;
        acc[2][0] += a2 * bv.x; acc[2][1] += a2 * bv.y; acc[2][2] += a2 * bv.z; acc[2][3] += a2 * bv.w;
        acc[3][0] += a3 * bv.x; acc[3][1] += a3 * bv.y; acc[3][2] += a3 * bv.z; acc[3][3] += a3 * bv.w;
    }
    size_t base = (size_t)bh * LL * SS + (size_t)l0 * SS + s0;
    #pragma unroll
    for (int i = 0; i < 4; i++)
        *(float4*)&g_scores[base + (size_t)(ty * 4 + i) * SS + (tx << 2)] =
            make_float4(acc[i][0], acc[i][1], acc[i][2], acc[i][3]);
}

// ==================== kernel 3: per-row tau + softmax (in place) ====================
__device__ __forceinline__ float wred_sum(float v) {
    #pragma unroll
    for (int o = 16; o; o >>= 1) v += __shfl_xor_sync(0xffffffffu, v, o);
    return v;
}
__device__ __forceinline__ float wred_max(float v) {
    #pragma unroll
    for (int o = 16; o; o >>= 1) v = fmaxf(v, __shfl_xor_sync(0xffffffffu, v, o));
    return v;
}

__global__ void __launch_bounds__(256) k_softmax() {
    size_t row = blockIdx.x;
    float* p = g_scores + row * (size_t)SS;
    int tid = threadIdx.x;
    float4 v0 = ((const float4*)p)[tid];
    float4 v1 = ((const float4*)p)[tid + 256];
    float xs[8] = { v0.x, v0.y, v0.z, v0.w, v1.x, v1.y, v1.z, v1.w };

    float mx = -1e30f, sm = 0.f, sq = 0.f;
    #pragma unroll
    for (int j = 0; j < 8; j++) { mx = fmaxf(mx, xs[j]); sm += xs[j]; sq += xs[j] * xs[j]; }

    __shared__ float sred[3][8];
    float wm = wred_max(mx), ws = wred_sum(sm), wq = wred_sum(sq);
    int lane = tid & 31, wid = tid >> 5;
    if (lane == 0) { sred[0][wid] = wm; sred[1][wid] = ws; sred[2][wid] = wq; }
    __syncthreads();
    float tm = -1e30f, ts = 0.f, tq = 0.f;
    #pragma unroll
    for (int w = 0; w < 8; w++) { tm = fmaxf(tm, sred[0][w]); ts += sred[1][w]; tq += sred[2][w]; }

    float var = (tq - ts * ts / (float)SS) / (float)(SS - 1);  // unbiased
    float tau = sqrtf(fmaxf(var, 0.f) + EPSF);
    float alpha = SCALEF / tau;
    float shift = alpha * tm;

    float es[8]; float psum = 0.f;
    #pragma unroll
    for (int j = 0; j < 8; j++) { es[j] = __expf(alpha * xs[j] - shift); psum += es[j]; }

    float wp = wred_sum(psum);
    __syncthreads();
    if (lane == 0) sred[0][wid] = wp;
    __syncthreads();
    float tp = 0.f;
    #pragma unroll
    for (int w = 0; w < 8; w++) tp += sred[0][w];
    float inv = 1.0f / tp;

    ((float4*)p)[tid]       = make_float4(es[0] * inv, es[1] * inv, es[2] * inv, es[3] * inv);
    ((float4*)p)[tid + 256] = make_float4(es[4] * inv, es[5] * inv, es[6] * inv, es[7] * inv);
}

// ==================== kernel 4: out = A @ V (per b,h) ====================
__global__ void __launch_bounds__(256) k_gemm_av(const float* __restrict__ V, float* __restrict__ O) {
    __shared__ float As[64][65];   // [l_local][s_local]
    __shared__ float Vs[64][64];   // [s_local][d]
    int l0 = blockIdx.x << 6;
    int bh = blockIdx.y;
    int b = bh >> 3, h = bh & 7;
    const float* Vb = V + (size_t)b * SS * HE + h * EE;
    const float* Ar = g_scores + (size_t)bh * LL * SS + (size_t)l0 * SS;
    int tid = threadIdx.x;
    int tx = tid & 15, ty = tid >> 4;
    int c = tid & 63, rg = tid >> 6;

    float acc[4][4] = {};
    for (int kt = 0; kt < SS; kt += 64) {
        #pragma unroll
        for (int r = 0; r < 64; r += 4)
            As[r + rg][c] = Ar[(size_t)(r + rg) * SS + kt + c];
        #pragma unroll
        for (int r = 0; r < 64; r += 4)
            Vs[r + rg][c] = Vb[(size_t)(kt + r + rg) * HE + c];
        __syncthreads();
        #pragma unroll 8
        for (int kk = 0; kk < 64; kk++) {
            float a0 = As[ty * 4 + 0][kk];
            float a1 = As[ty * 4 + 1][kk];
            float a2 = As[ty * 4 + 2][kk];
            float a3 = As[ty * 4 + 3][kk];
            float4 bv = *(const float4*)&Vs[kk][tx << 2];
            acc[0][0] += a0 * bv.x; acc[0][1] += a0 * bv.y; acc[0][2] += a0 * bv.z; acc[0][3] += a0 * bv.w;
            acc[1][0] += a1 * bv.x; acc[1][1] += a1 * bv.y; acc[1][2] += a1 * bv.z; acc[1][3] += a1 * bv.w;
            acc[2][0] += a2 * bv.x; acc[2][1] += a2 * bv.y; acc[2][2] += a2 * bv.z; acc[2][3] += a2 * bv.w;
            acc[3][0] += a3 * bv.x; acc[3][1] += a3 * bv.y; acc[3][2] += a3 * bv.z; acc[3][3] += a3 * bv.w;
        }
        __syncthreads();
    }
    // out[b][l][h][d]
    #pragma unroll
    for (int i = 0; i < 4; i++) {
        size_t oi = ((size_t)((size_t)b * LL + l0 + ty * 4 + i) * HH + h) * EE + (tx << 2);
        *(float4*)&O[oi] = make_float4(acc[i][0], acc[i][1], acc[i][2], acc[i][3]);
    }
}

// ==================== launch ====================
extern "C" void kernel_launch(void* const* d_in, const int* in_sizes, int n_in,
                              void* d_out, int out_size) {
    const float* q  = (const float*)d_in[0];
    const float* k  = (const float*)d_in[1];
    const float* v  = (const float*)d_in[2];
    // d_in[3]: attn_mask (bool, unused — mask_flag=False)
    const float* dw = (const float*)d_in[4];
    const float* dp = (const float*)d_in[5];
    float* out = (float*)d_out;

    k_transform<<<dim3(BB * LL, 2), 512>>>(q, k, dw, dp);
    k_gemm_qk  <<<dim3(SS / 64, LL / 64, BH), 256>>>();
    k_softmax  <<<dim3(BH * LL), 256>>>();
    k_gemm_av  <<<dim3(LL / 64, BH), 256>>>(v, out);
}

// round 3
// speedup vs baseline: 1.6695x; 1.6695x over previous
#include <cuda_runtime.h>
#include <math.h>
#include <stdint.h>

#define BB 4
#define LL 2048
#define SS 2048
#define HH 8
#define EE 64
#define HE 512          // HH*EE
#define BH 32           // BB*HH
#define NELEM (BB*LL*HH*EE)
#define EPSF 1e-6f
#define SCALEF 0.125f   // 1/sqrt(64)

// -------- device scratch (alloc-free rule: __device__ globals) --------
__device__ float g_qt[NELEM];       // tf32-rounded transformed Q
__device__ float g_kt[NELEM];       // tf32-rounded transformed K
__device__ float g_scores[(size_t)BH * LL * SS];   // 512 MB

__device__ __forceinline__ uint32_t f2tf(float f) {
    uint32_t r;
    asm("cvt.rna.tf32.f32 %0, %1;" : "=r"(r) : "f"(f));
    return r;
}

__device__ __forceinline__ void mma8(float* c, const uint32_t* a, const uint32_t* b) {
    asm volatile("mma.sync.aligned.m16n8k8.row.col.f32.tf32.tf32.f32 "
                 "{%0,%1,%2,%3},{%4,%5,%6,%7},{%8,%9},{%0,%1,%2,%3};"
                 : "+f"(c[0]), "+f"(c[1]), "+f"(c[2]), "+f"(c[3])
                 : "r"(a[0]), "r"(a[1]), "r"(a[2]), "r"(a[3]), "r"(b[0]), "r"(b[1]));
}

// ==================== kernel 1: transform; std over HEADS (axis=-2), tf32-rounded out ====================
__global__ void __launch_bounds__(512) k_transform(const float* __restrict__ q,
                                                   const float* __restrict__ k,
                                                   const float* __restrict__ dw,
                                                   const float* __restrict__ dp) {
    int sel = blockIdx.y;
    const float* x = (sel ? k : q) + (size_t)blockIdx.x * HE;
    float* o = (sel ? g_kt : g_qt) + (size_t)blockIdx.x * HE;
    float w = dw[0];
    float p = dp[0];
    int tid = threadIdx.x;          // h*64 + e
    int e = tid & 63;
    float v = x[tid];

    __shared__ float s1[512];
    __shared__ float istd[64];
    s1[tid] = v;
    __syncthreads();
    if (tid < 64) {
        float s = 0.f, ss = 0.f;
        #pragma unroll
        for (int h = 0; h < 8; h++) {
            float u = s1[h * 64 + tid];
            s += u; ss += u * u;
        }
        float mean = s * 0.125f;
        float var = (ss - s * mean) * (1.0f / 7.0f);    // unbiased n=8
        istd[tid] = 1.0f / (sqrtf(fmaxf(var, 0.f)) + EPSF);
    }
    __syncthreads();
    o[tid] = __uint_as_float(f2tf(tanhf(v * istd[e] * w) * p));
}

// ==================== kernel 2: scores = qt @ kt^T  (tf32 mma) ====================
#define QKPAD 68
__global__ void __launch_bounds__(256, 2) k_gemm_qk() {
    extern __shared__ uint32_t sh[];
    uint32_t* Qs = sh;                    // [128][QKPAD]
    uint32_t* Ks = sh + 128 * QKPAD;      // [128][QKPAD]
    int bh = blockIdx.z;
    int l0 = blockIdx.y << 7, s0 = blockIdx.x << 7;
    const float* Q = g_qt + (size_t)(bh >> 3) * LL * HE + (bh & 7) * EE;
    const float* K = g_kt + (size_t)(bh >> 3) * LL * HE + (bh & 7) * EE;
    int tid = threadIdx.x;

    {   // fills: 128 rows x 64 cols each, bits already tf32-rounded
        int frow = tid >> 1;
        int fcb = (tid & 1) * 8;
        #pragma unroll
        for (int j = 0; j < 8; j++) {
            int c4 = fcb + j;
            float4 v = *(const float4*)(Q + (size_t)(l0 + frow) * HE + c4 * 4);
            *(uint4*)&Qs[frow * QKPAD + c4 * 4] =
                make_uint4(__float_as_uint(v.x), __float_as_uint(v.y), __float_as_uint(v.z), __float_as_uint(v.w));
            float4 u = *(const float4*)(K + (size_t)(s0 + frow) * HE + c4 * 4);
            *(uint4*)&Ks[frow * QKPAD + c4 * 4] =
                make_uint4(__float_as_uint(u.x), __float_as_uint(u.y), __float_as_uint(u.z), __float_as_uint(u.w));
        }
    }
    __syncthreads();

    int lane = tid & 31, wid = tid >> 5;
    int wr = (wid >> 2) * 64;     // warp row base (2 rows of warps)
    int wc = (wid & 3) * 32;      // warp col base (4 cols of warps)
    int g = lane >> 2, t = lane & 3;

    float acc[4][4][4];
    #pragma unroll
    for (int i = 0; i < 4; i++)
        #pragma unroll
        for (int j = 0; j < 4; j++)
            #pragma unroll
            for (int r = 0; r < 4; r++) acc[i][j][r] = 0.f;

    #pragma unroll
    for (int k0 = 0; k0 < 64; k0 += 8) {
        uint32_t a[4][4], b[4][2];
        #pragma unroll
        for (int mi = 0; mi < 4; mi++) {
            const uint32_t* p = &Qs[(wr + mi * 16 + g) * QKPAD + k0 + t];
            a[mi][0] = p[0]; a[mi][1] = p[8 * QKPAD]; a[mi][2] = p[4]; a[mi][3] = p[8 * QKPAD + 4];
        }
        #pragma unroll
        for (int ni = 0; ni < 4; ni++) {
            const uint32_t* p = &Ks[(wc + ni * 8 + g) * QKPAD + k0 + t];
            b[ni][0] = p[0]; b[ni][1] = p[4];
        }
        #pragma unroll
        for (int mi = 0; mi < 4; mi++)
            #pragma unroll
            for (int ni = 0; ni < 4; ni++)
                mma8(acc[mi][ni], a[mi], b[ni]);
    }

    size_t base = (size_t)bh * LL * SS;
    #pragma unroll
    for (int mi = 0; mi < 4; mi++) {
        int r0 = l0 + wr + mi * 16 + g;
        #pragma unroll
        for (int ni = 0; ni < 4; ni++) {
            int c = s0 + wc + ni * 8 + 2 * t;
            *(float2*)&g_scores[base + (size_t)r0 * SS + c] = make_float2(acc[mi][ni][0], acc[mi][ni][1]);
            *(float2*)&g_scores[base + (size_t)(r0 + 8) * SS + c] = make_float2(acc[mi][ni][2], acc[mi][ni][3]);
        }
    }
}

// ==================== kernel 3: per-row tau + softmax (in place, tf32-rounded out) ====================
__device__ __forceinline__ float wred_sum(float v) {
    #pragma unroll
    for (int o = 16; o; o >>= 1) v += __shfl_xor_sync(0xffffffffu, v, o);
    return v;
}
__device__ __forceinline__ float wred_max(float v) {
    #pragma unroll
    for (int o = 16; o; o >>= 1) v = fmaxf(v, __shfl_xor_sync(0xffffffffu, v, o));
    return v;
}

__global__ void __launch_bounds__(256) k_softmax() {
    size_t row = blockIdx.x;
    float* p = g_scores + row * (size_t)SS;
    int tid = threadIdx.x;
    float4 v0 = ((const float4*)p)[tid];
    float4 v1 = ((const float4*)p)[tid + 256];
    float xs[8] = { v0.x, v0.y, v0.z, v0.w, v1.x, v1.y, v1.z, v1.w };

    float mx = -1e30f, sm = 0.f, sq = 0.f;
    #pragma unroll
    for (int j = 0; j < 8; j++) { mx = fmaxf(mx, xs[j]); sm += xs[j]; sq += xs[j] * xs[j]; }

    __shared__ float sred[3][8];
    float wm = wred_max(mx), ws = wred_sum(sm), wq = wred_sum(sq);
    int lane = tid & 31, wid = tid >> 5;
    if (lane == 0) { sred[0][wid] = wm; sred[1][wid] = ws; sred[2][wid] = wq; }
    __syncthreads();
    float tm = -1e30f, ts = 0.f, tq = 0.f;
    #pragma unroll
    for (int w = 0; w < 8; w++) { tm = fmaxf(tm, sred[0][w]); ts += sred[1][w]; tq += sred[2][w]; }

    float var = (tq - ts * ts / (float)SS) / (float)(SS - 1);  // unbiased
    float tau = sqrtf(fmaxf(var, 0.f) + EPSF);
    float alpha = SCALEF / tau;
    float shift = alpha * tm;

    float es[8]; float psum = 0.f;
    #pragma unroll
    for (int j = 0; j < 8; j++) { es[j] = __expf(alpha * xs[j] - shift); psum += es[j]; }

    float wp = wred_sum(psum);
    __syncthreads();
    if (lane == 0) sred[0][wid] = wp;
    __syncthreads();
    float tp = 0.f;
    #pragma unroll
    for (int w = 0; w < 8; w++) tp += sred[0][w];
    float inv = 1.0f / tp;

    uint4 o0, o1;
    o0.x = f2tf(es[0] * inv); o0.y = f2tf(es[1] * inv); o0.z = f2tf(es[2] * inv); o0.w = f2tf(es[3] * inv);
    o1.x = f2tf(es[4] * inv); o1.y = f2tf(es[5] * inv); o1.z = f2tf(es[6] * inv); o1.w = f2tf(es[7] * inv);
    ((uint4*)p)[tid]       = o0;
    ((uint4*)p)[tid + 256] = o1;
}

// ==================== kernel 4: out = A @ V  (tf32 mma) ====================
#define APAD 68
#define VPAD 76
__global__ void __launch_bounds__(128) k_gemm_av(const float* __restrict__ V, float* __restrict__ O) {
    __shared__ uint32_t As[64 * APAD];   // [l][s] 17.4 KB
    __shared__ uint32_t Vs[64 * VPAD];   // [s][d] 19.5 KB
    int l0 = blockIdx.x << 6;
    int bh = blockIdx.y;
    int b = bh >> 3, h = bh & 7;
    const float* Vb = V + (size_t)b * SS * HE + h * EE;
    const float* Ar = g_scores + (size_t)bh * LL * SS + (size_t)l0 * SS;
    int tid = threadIdx.x;
    int frow = tid >> 1, fcb = (tid & 1) * 8;
    int lane = tid & 31, wid = tid >> 5;
    int wr = (wid & 1) * 32, wc = (wid >> 1) * 32;
    int g = lane >> 2, t = lane & 3;

    float acc[2][4][4];
    #pragma unroll
    for (int i = 0; i < 2; i++)
        #pragma unroll
        for (int j = 0; j < 4; j++)
            #pragma unroll
            for (int r = 0; r < 4; r++) acc[i][j][r] = 0.f;

    for (int kt = 0; kt < SS; kt += 64) {
        #pragma unroll
        for (int j = 0; j < 8; j++) {
            int c4 = fcb + j;
            float4 av = *(const float4*)(Ar + (size_t)frow * SS + kt + c4 * 4);   // pre-rounded tf32
            *(uint4*)&As[frow * APAD + c4 * 4] =
                make_uint4(__float_as_uint(av.x), __float_as_uint(av.y), __float_as_uint(av.z), __float_as_uint(av.w));
            float4 vv = *(const float4*)(Vb + (size_t)(kt + frow) * HE + c4 * 4);
            *(uint4*)&Vs[frow * VPAD + c4 * 4] =
                make_uint4(f2tf(vv.x), f2tf(vv.y), f2tf(vv.z), f2tf(vv.w));
        }
        __syncthreads();
        #pragma unroll
        for (int k0 = 0; k0 < 64; k0 += 8) {
            uint32_t a[2][4], bf[4][2];
            #pragma unroll
            for (int mi = 0; mi < 2; mi++) {
                const uint32_t* p = &As[(wr + mi * 16 + g) * APAD + k0 + t];
                a[mi][0] = p[0]; a[mi][1] = p[8 * APAD]; a[mi][2] = p[4]; a[mi][3] = p[8 * APAD + 4];
            }
            #pragma unroll
            for (int ni = 0; ni < 4; ni++) {
                bf[ni][0] = Vs[(k0 + t) * VPAD + wc + ni * 8 + g];
                bf[ni][1] = Vs[(k0 + t + 4) * VPAD + wc + ni * 8 + g];
            }
            #pragma unroll
            for (int mi = 0; mi < 2; mi++)
                #pragma unroll
                for (int ni = 0; ni < 4; ni++)
                    mma8(acc[mi][ni], a[mi], bf[ni]);
        }
        __syncthreads();
    }

    #pragma unroll
    for (int mi = 0; mi < 2; mi++) {
        int r = l0 + wr + mi * 16 + g;
        #pragma unroll
        for (int ni = 0; ni < 4; ni++) {
            int d = wc + ni * 8 + 2 * t;
            size_t o0 = ((size_t)((size_t)b * LL + r) * HH + h) * EE + d;
            *(float2*)&O[o0] = make_float2(acc[mi][ni][0], acc[mi][ni][1]);
            size_t o1 = ((size_t)((size_t)b * LL + r + 8) * HH + h) * EE + d;
            *(float2*)&O[o1] = make_float2(acc[mi][ni][2], acc[mi][ni][3]);
        }
    }
}

// ==================== launch ====================
extern "C" void kernel_launch(void* const* d_in, const int* in_sizes, int n_in,
                              void* d_out, int out_size) {
    const float* q  = (const float*)d_in[0];
    const float* k  = (const float*)d_in[1];
    const float* v  = (const float*)d_in[2];
    const float* dw = (const float*)d_in[4];
    const float* dp = (const float*)d_in[5];
    float* out = (float*)d_out;

    const int qk_smem = 2 * 128 * QKPAD * 4;   // 69632 B
    cudaFuncSetAttribute(k_gemm_qk, cudaFuncAttributeMaxDynamicSharedMemorySize, qk_smem);

    k_transform<<<dim3(BB * LL, 2), 512>>>(q, k, dw, dp);
    k_gemm_qk  <<<dim3(SS / 128, LL / 128, BH), 256, qk_smem>>>();
    k_softmax  <<<dim3(BH * LL), 256>>>();
    k_gemm_av  <<<dim3(LL / 64, BH), 128>>>(v, out);
}

// round 5
// speedup vs baseline: 2.7526x; 1.6487x over previous
#include <cuda_runtime.h>
#include <math.h>
#include <stdint.h>

#define BB 4
#define LL 2048
#define SS 2048
#define HH 8
#define EE 64
#define HE 512          // HH*EE
#define BH 32           // BB*HH
#define NELEM (BB*LL*HH*EE)
#define EPSF 1e-6f
#define SCALEF 0.125f   // 1/sqrt(64)

// -------- device scratch (alloc-free rule: __device__ globals) --------
__device__ float g_qt[NELEM];       // tf32-rounded transformed Q
__device__ float g_kt[NELEM];       // tf32-rounded transformed K
__device__ float g_scores[(size_t)BH * LL * SS];   // 512 MB

__device__ __forceinline__ uint32_t f2tf(float f) {
    uint32_t r;
    asm("cvt.rna.tf32.f32 %0, %1;" : "=r"(r) : "f"(f));
    return r;
}

__device__ __forceinline__ void mma8(float* c, const uint32_t* a, const uint32_t* b) {
    asm volatile("mma.sync.aligned.m16n8k8.row.col.f32.tf32.tf32.f32 "
                 "{%0,%1,%2,%3},{%4,%5,%6,%7},{%8,%9},{%0,%1,%2,%3};"
                 : "+f"(c[0]), "+f"(c[1]), "+f"(c[2]), "+f"(c[3])
                 : "r"(a[0]), "r"(a[1]), "r"(a[2]), "r"(a[3]), "r"(b[0]), "r"(b[1]));
}

__device__ __forceinline__ void cpasync16(uint32_t dst, const void* src) {
    asm volatile("cp.async.cg.shared.global [%0], [%1], 16;" :: "r"(dst), "l"(src));
}
__device__ __forceinline__ void cp_commit() { asm volatile("cp.async.commit_group;"); }
template<int N> __device__ __forceinline__ void cp_wait() {
    asm volatile("cp.async.wait_group %0;" :: "n"(N));
}

// ==================== kernel 1: transform; std over HEADS (axis=-2), tf32-rounded out ====================
__global__ void __launch_bounds__(512) k_transform(const float* __restrict__ q,
                                                   const float* __restrict__ k,
                                                   const float* __restrict__ dw,
                                                   const float* __restrict__ dp) {
    int sel = blockIdx.y;
    const float* x = (sel ? k : q) + (size_t)blockIdx.x * HE;
    float* o = (sel ? g_kt : g_qt) + (size_t)blockIdx.x * HE;
    float w = dw[0];
    float p = dp[0];
    int tid = threadIdx.x;          // h*64 + e
    int e = tid & 63;
    float v = x[tid];

    __shared__ float s1[512];
    __shared__ float istd[64];
    s1[tid] = v;
    __syncthreads();
    if (tid < 64) {
        float s = 0.f, ss = 0.f;
        #pragma unroll
        for (int h = 0; h < 8; h++) {
            float u = s1[h * 64 + tid];
            s += u; ss += u * u;
        }
        float mean = s * 0.125f;
        float var = (ss - s * mean) * (1.0f / 7.0f);    // unbiased n=8
        istd[tid] = 1.0f / (sqrtf(fmaxf(var, 0.f)) + EPSF);
    }
    __syncthreads();
    o[tid] = __uint_as_float(f2tf(tanhf(v * istd[e] * w) * p));
}

// ==================== kernel 2: scores = qt @ kt^T  (tf32 mma) ====================
#define QKPAD 68
__global__ void __launch_bounds__(256, 2) k_gemm_qk() {
    extern __shared__ uint32_t shqk[];
    uint32_t* Qs = shqk;                    // [128][QKPAD]
    uint32_t* Ks = shqk + 128 * QKPAD;      // [128][QKPAD]
    int bh = blockIdx.z;
    int l0 = blockIdx.y << 7, s0 = blockIdx.x << 7;
    const float* Q = g_qt + (size_t)(bh >> 3) * LL * HE + (bh & 7) * EE;
    const float* K = g_kt + (size_t)(bh >> 3) * LL * HE + (bh & 7) * EE;
    int tid = threadIdx.x;

    {   // fills: 128 rows x 64 cols each, bits already tf32-rounded
        int frow = tid >> 1;
        int fcb = (tid & 1) * 8;
        #pragma unroll
        for (int j = 0; j < 8; j++) {
            int c4 = fcb + j;
            float4 v = *(const float4*)(Q + (size_t)(l0 + frow) * HE + c4 * 4);
            *(uint4*)&Qs[frow * QKPAD + c4 * 4] =
                make_uint4(__float_as_uint(v.x), __float_as_uint(v.y), __float_as_uint(v.z), __float_as_uint(v.w));
            float4 u = *(const float4*)(K + (size_t)(s0 + frow) * HE + c4 * 4);
            *(uint4*)&Ks[frow * QKPAD + c4 * 4] =
                make_uint4(__float_as_uint(u.x), __float_as_uint(u.y), __float_as_uint(u.z), __float_as_uint(u.w));
        }
    }
    __syncthreads();

    int lane = tid & 31, wid = tid >> 5;
    int wr = (wid >> 2) * 64;     // warp row base
    int wc = (wid & 3) * 32;      // warp col base
    int g = lane >> 2, t = lane & 3;

    float acc[4][4][4];
    #pragma unroll
    for (int i = 0; i < 4; i++)
        #pragma unroll
        for (int j = 0; j < 4; j++)
            #pragma unroll
            for (int r = 0; r < 4; r++) acc[i][j][r] = 0.f;

    #pragma unroll
    for (int k0 = 0; k0 < 64; k0 += 8) {
        uint32_t a[4][4], b[4][2];
        #pragma unroll
        for (int mi = 0; mi < 4; mi++) {
            const uint32_t* p = &Qs[(wr + mi * 16 + g) * QKPAD + k0 + t];
            a[mi][0] = p[0]; a[mi][1] = p[8 * QKPAD]; a[mi][2] = p[4]; a[mi][3] = p[8 * QKPAD + 4];
        }
        #pragma unroll
        for (int ni = 0; ni < 4; ni++) {
            const uint32_t* p = &Ks[(wc + ni * 8 + g) * QKPAD + k0 + t];
            b[ni][0] = p[0]; b[ni][1] = p[4];
        }
        #pragma unroll
        for (int mi = 0; mi < 4; mi++)
            #pragma unroll
            for (int ni = 0; ni < 4; ni++)
                mma8(acc[mi][ni], a[mi], b[ni]);
    }

    size_t base = (size_t)bh * LL * SS;
    #pragma unroll
    for (int mi = 0; mi < 4; mi++) {
        int r0 = l0 + wr + mi * 16 + g;
        #pragma unroll
        for (int ni = 0; ni < 4; ni++) {
            int c = s0 + wc + ni * 8 + 2 * t;
            *(float2*)&g_scores[base + (size_t)r0 * SS + c] = make_float2(acc[mi][ni][0], acc[mi][ni][1]);
            *(float2*)&g_scores[base + (size_t)(r0 + 8) * SS + c] = make_float2(acc[mi][ni][2], acc[mi][ni][3]);
        }
    }
}

// ==================== kernel 3: per-row tau + softmax (in place, tf32-rounded out) ====================
__device__ __forceinline__ float wred_sum(float v) {
    #pragma unroll
    for (int o = 16; o; o >>= 1) v += __shfl_xor_sync(0xffffffffu, v, o);
    return v;
}
__device__ __forceinline__ float wred_max(float v) {
    #pragma unroll
    for (int o = 16; o; o >>= 1) v = fmaxf(v, __shfl_xor_sync(0xffffffffu, v, o));
    return v;
}

__global__ void __launch_bounds__(256) k_softmax() {
    size_t row = blockIdx.x;
    float* p = g_scores + row * (size_t)SS;
    int tid = threadIdx.x;
    float4 v0 = ((const float4*)p)[tid];
    float4 v1 = ((const float4*)p)[tid + 256];
    float xs[8] = { v0.x, v0.y, v0.z, v0.w, v1.x, v1.y, v1.z, v1.w };

    float mx = -1e30f, sm = 0.f, sq = 0.f;
    #pragma unroll
    for (int j = 0; j < 8; j++) { mx = fmaxf(mx, xs[j]); sm += xs[j]; sq += xs[j] * xs[j]; }

    __shared__ float sred[3][8];
    float wm = wred_max(mx), ws = wred_sum(sm), wq = wred_sum(sq);
    int lane = tid & 31, wid = tid >> 5;
    if (lane == 0) { sred[0][wid] = wm; sred[1][wid] = ws; sred[2][wid] = wq; }
    __syncthreads();
    float tm = -1e30f, ts = 0.f, tq = 0.f;
    #pragma unroll
    for (int w = 0; w < 8; w++) { tm = fmaxf(tm, sred[0][w]); ts += sred[1][w]; tq += sred[2][w]; }

    float var = (tq - ts * ts / (float)SS) / (float)(SS - 1);  // unbiased
    float tau = sqrtf(fmaxf(var, 0.f) + EPSF);
    float alpha = SCALEF / tau;
    float shift = alpha * tm;

    float es[8]; float psum = 0.f;
    #pragma unroll
    for (int j = 0; j < 8; j++) { es[j] = __expf(alpha * xs[j] - shift); psum += es[j]; }

    float wp = wred_sum(psum);
    __syncthreads();
    if (lane == 0) sred[0][wid] = wp;
    __syncthreads();
    float tp = 0.f;
    #pragma unroll
    for (int w = 0; w < 8; w++) tp += sred[0][w];
    float inv = 1.0f / tp;

    uint4 o0, o1;
    o0.x = f2tf(es[0] * inv); o0.y = f2tf(es[1] * inv); o0.z = f2tf(es[2] * inv); o0.w = f2tf(es[3] * inv);
    o1.x = f2tf(es[4] * inv); o1.y = f2tf(es[5] * inv); o1.z = f2tf(es[6] * inv); o1.w = f2tf(es[7] * inv);
    ((uint4*)p)[tid]       = o0;
    ((uint4*)p)[tid + 256] = o1;
}

// ==================== kernel 4: out = A @ V  (tf32 mma, cp.async double-buffered) ====================
#define APAD 36    // 32+4: A [row][k] fragment reads conflict-free (stride ≡ 4 mod 32)
#define VPAD 72    // 64+8: V [k][d] fragment reads conflict-free (stride ≡ 8 mod 32)
#define AVSMEM ((2 * 128 * APAD + 2 * 32 * VPAD) * 4)   // 55296 B

__global__ void __launch_bounds__(256, 3) k_gemm_av(const float* __restrict__ V, float* __restrict__ O) {
    extern __shared__ uint32_t shav[];
    uint32_t* As = shav;                    // [2][128*APAD]
    uint32_t* Vs = shav + 2 * 128 * APAD;   // [2][32*VPAD]
    int l0 = blockIdx.x << 7;
    int bh = blockIdx.y;
    int b = bh >> 3, h = bh & 7;
    const float* Vb = V + (size_t)b * SS * HE + h * EE;
    const float* Ar = g_scores + (size_t)bh * LL * SS + (size_t)l0 * SS;
    int tid = threadIdx.x;

    // fill indexing: one 16B cp.async per thread per pass
    int afr = tid >> 3, afc = (tid & 7) * 4;     // A: 32 rows/pass × 4 passes (128 rows × 32 cols)
    int vfr = tid >> 4, vfc = (tid & 15) * 4;    // V: 16 rows/pass × 2 passes (32 rows × 64 cols)
    uint32_t asb = (uint32_t)__cvta_generic_to_shared(As);
    uint32_t vsb = (uint32_t)__cvta_generic_to_shared(Vs);

    int lane = tid & 31, wid = tid >> 5;
    int wr = (wid & 3) * 32;        // 4 row-groups of warps
    int wc = (wid >> 2) * 32;       // 2 col-groups of warps
    int g = lane >> 2, t4 = lane & 3;

    float acc[2][4][4];
    #pragma unroll
    for (int i = 0; i < 2; i++)
        #pragma unroll
        for (int j = 0; j < 4; j++)
            #pragma unroll
            for (int r = 0; r < 4; r++) acc[i][j][r] = 0.f;

    // issue chunk tt into buffer buf
    #define ISSUE(tt, buf)                                                              \
        do {                                                                            \
            const float* asrc = Ar + (tt) * 32;                                         \
            _Pragma("unroll")                                                           \
            for (int pp = 0; pp < 4; pp++) {                                            \
                int r = afr + pp * 32;                                                  \
                cpasync16(asb + (uint32_t)((buf) * 128 * APAD + r * APAD + afc) * 4,    \
                          asrc + (size_t)r * SS + afc);                                 \
            }                                                                           \
            const float* vsrc = Vb + (size_t)((tt) * 32) * HE;                          \
            _Pragma("unroll")                                                           \
            for (int pp = 0; pp < 2; pp++) {                                            \
                int r = vfr + pp * 16;                                                  \
                cpasync16(vsb + (uint32_t)((buf) * 32 * VPAD + r * VPAD + vfc) * 4,     \
                          vsrc + (size_t)r * HE + vfc);                                 \
            }                                                                           \
        } while (0)

    ISSUE(0, 0);
    cp_commit();

    for (int tt = 0; tt < 64; tt++) {
        int buf = tt & 1;
        if (tt + 1 < 64) {
            ISSUE(tt + 1, buf ^ 1);
            cp_commit();
            cp_wait<1>();
        } else {
            cp_wait<0>();
        }
        __syncthreads();

        const uint32_t* Ab = As + buf * 128 * APAD;
        const uint32_t* Vf = Vs + buf * 32 * VPAD;
        #pragma unroll
        for (int k0 = 0; k0 < 32; k0 += 8) {
            uint32_t a[2][4], bf[4][2];
            #pragma unroll
            for (int mi = 0; mi < 2; mi++) {
                const uint32_t* p = &Ab[(wr + mi * 16 + g) * APAD + k0 + t4];
                a[mi][0] = p[0]; a[mi][1] = p[8 * APAD]; a[mi][2] = p[4]; a[mi][3] = p[8 * APAD + 4];
            }
            #pragma unroll
            for (int ni = 0; ni < 4; ni++) {
                bf[ni][0] = Vf[(k0 + t4) * VPAD + wc + ni * 8 + g];
                bf[ni][1] = Vf[(k0 + t4 + 4) * VPAD + wc + ni * 8 + g];
            }
            #pragma unroll
            for (int mi = 0; mi < 2; mi++)
                #pragma unroll
                for (int ni = 0; ni < 4; ni++)
                    mma8(acc[mi][ni], a[mi], bf[ni]);
        }
        __syncthreads();
    }

    #pragma unroll
    for (int mi = 0; mi < 2; mi++) {
        int r = l0 + wr + mi * 16 + g;
        #pragma unroll
        for (int ni = 0; ni < 4; ni++) {
            int d = wc + ni * 8 + 2 * t4;
            size_t o0 = ((size_t)((size_t)b * LL + r) * HH + h) * EE + d;
            *(float2*)&O[o0] = make_float2(acc[mi][ni][0], acc[mi][ni][1]);
            size_t o1 = ((size_t)((size_t)b * LL + r + 8) * HH + h) * EE + d;
            *(float2*)&O[o1] = make_float2(acc[mi][ni][2], acc[mi][ni][3]);
        }
    }
}

// ==================== launch ====================
extern "C" void kernel_launch(void* const* d_in, const int* in_sizes, int n_in,
                              void* d_out, int out_size) {
    const float* q  = (const float*)d_in[0];
    const float* k  = (const float*)d_in[1];
    const float* v  = (const float*)d_in[2];
    const float* dw = (const float*)d_in[4];
    const float* dp = (const float*)d_in[5];
    float* out = (float*)d_out;

    const int qk_smem = 2 * 128 * QKPAD * 4;   // 69632 B
    cudaFuncSetAttribute(k_gemm_qk, cudaFuncAttributeMaxDynamicSharedMemorySize, qk_smem);
    cudaFuncSetAttribute(k_gemm_av, cudaFuncAttributeMaxDynamicSharedMemorySize, AVSMEM);

    k_transform<<<dim3(BB * LL, 2), 512>>>(q, k, dw, dp);
    k_gemm_qk  <<<dim3(SS / 128, LL / 128, BH), 256, qk_smem>>>();
    k_softmax  <<<dim3(BH * LL), 256>>>();
    k_gemm_av  <<<dim3(LL / 128, BH), 256, AVSMEM>>>(v, out);
}

// round 6
// speedup vs baseline: 3.2246x; 1.1715x over previous
#include <cuda_runtime.h>
#include <math.h>
#include <stdint.h>

#define BB 4
#define LL 2048
#define SS 2048
#define HH 8
#define EE 64
#define HE 512          // HH*EE
#define BH 32           // BB*HH
#define NELEM (BB*LL*HH*EE)
#define NROWS (BH * LL)      // 65536 attention rows
#define NSTILE 16            // SS/128 score tiles per row
#define EPSF 1e-6f
#define SCALEF 0.125f   // 1/sqrt(64)

// -------- device scratch (alloc-free rule: __device__ globals) --------
__device__ float g_qt[NELEM];       // tf32-rounded transformed Q
__device__ float g_kt[NELEM];       // tf32-rounded transformed K
__device__ float g_scores[(size_t)BH * LL * SS];   // 512 MB, raw fp32 scores
__device__ float2 g_pstat[(size_t)NROWS * NSTILE]; // per (row, s-tile): (sum, sumsq)
__device__ float2 g_alsh[NROWS];                   // per row: (alpha, shift)

__device__ __forceinline__ uint32_t f2tf(float f) {
    uint32_t r;
    asm("cvt.rna.tf32.f32 %0, %1;" : "=r"(r) : "f"(f));
    return r;
}

__device__ __forceinline__ void mma8(float* c, const uint32_t* a, const uint32_t* b) {
    asm volatile("mma.sync.aligned.m16n8k8.row.col.f32.tf32.tf32.f32 "
                 "{%0,%1,%2,%3},{%4,%5,%6,%7},{%8,%9},{%0,%1,%2,%3};"
                 : "+f"(c[0]), "+f"(c[1]), "+f"(c[2]), "+f"(c[3])
                 : "r"(a[0]), "r"(a[1]), "r"(a[2]), "r"(a[3]), "r"(b[0]), "r"(b[1]));
}

__device__ __forceinline__ void cpasync16(uint32_t dst, const void* src) {
    asm volatile("cp.async.cg.shared.global [%0], [%1], 16;" :: "r"(dst), "l"(src));
}
__device__ __forceinline__ void cp_commit() { asm volatile("cp.async.commit_group;"); }
template<int N> __device__ __forceinline__ void cp_wait() {
    asm volatile("cp.async.wait_group %0;" :: "n"(N));
}

// ==================== kernel 1: transform; std over HEADS (axis=-2), tf32-rounded out ====================
__global__ void __launch_bounds__(512) k_transform(const float* __restrict__ q,
                                                   const float* __restrict__ k,
                                                   const float* __restrict__ dw,
                                                   const float* __restrict__ dp) {
    int sel = blockIdx.y;
    const float* x = (sel ? k : q) + (size_t)blockIdx.x * HE;
    float* o = (sel ? g_kt : g_qt) + (size_t)blockIdx.x * HE;
    float w = dw[0];
    float p = dp[0];
    int tid = threadIdx.x;          // h*64 + e
    int e = tid & 63;
    float v = x[tid];

    __shared__ float s1[512];
    __shared__ float istd[64];
    s1[tid] = v;
    __syncthreads();
    if (tid < 64) {
        float s = 0.f, ss = 0.f;
        #pragma unroll
        for (int h = 0; h < 8; h++) {
            float u = s1[h * 64 + tid];
            s += u; ss += u * u;
        }
        float mean = s * 0.125f;
        float var = (ss - s * mean) * (1.0f / 7.0f);    // unbiased n=8
        istd[tid] = 1.0f / (sqrtf(fmaxf(var, 0.f)) + EPSF);
    }
    __syncthreads();
    o[tid] = __uint_as_float(f2tf(tanhf(v * istd[e] * w) * p));
}

// ==================== kernel 2: scores = qt @ kt^T  (tf32 mma) + per-tile row stats ====================
#define QKPAD 68
__global__ void __launch_bounds__(256, 2) k_gemm_qk() {
    extern __shared__ uint32_t shqk[];
    uint32_t* Qs = shqk;                    // [128][QKPAD]
    uint32_t* Ks = shqk + 128 * QKPAD;      // [128][QKPAD]
    int bh = blockIdx.z;
    int l0 = blockIdx.y << 7, s0 = blockIdx.x << 7;
    const float* Q = g_qt + (size_t)(bh >> 3) * LL * HE + (bh & 7) * EE;
    const float* K = g_kt + (size_t)(bh >> 3) * LL * HE + (bh & 7) * EE;
    int tid = threadIdx.x;

    {   // fills: 128 rows x 64 cols each, bits already tf32-rounded
        int frow = tid >> 1;
        int fcb = (tid & 1) * 8;
        #pragma unroll
        for (int j = 0; j < 8; j++) {
            int c4 = fcb + j;
            float4 v = *(const float4*)(Q + (size_t)(l0 + frow) * HE + c4 * 4);
            *(uint4*)&Qs[frow * QKPAD + c4 * 4] =
                make_uint4(__float_as_uint(v.x), __float_as_uint(v.y), __float_as_uint(v.z), __float_as_uint(v.w));
            float4 u = *(const float4*)(K + (size_t)(s0 + frow) * HE + c4 * 4);
            *(uint4*)&Ks[frow * QKPAD + c4 * 4] =
                make_uint4(__float_as_uint(u.x), __float_as_uint(u.y), __float_as_uint(u.z), __float_as_uint(u.w));
        }
    }
    __syncthreads();

    int lane = tid & 31, wid = tid >> 5;
    int wr = (wid >> 2) * 64;     // warp row base (2 groups)
    int wc = (wid & 3) * 32;      // warp col base (4 groups)
    int g = lane >> 2, t = lane & 3;

    float acc[4][4][4];
    #pragma unroll
    for (int i = 0; i < 4; i++)
        #pragma unroll
        for (int j = 0; j < 4; j++)
            #pragma unroll
            for (int r = 0; r < 4; r++) acc[i][j][r] = 0.f;

    #pragma unroll
    for (int k0 = 0; k0 < 64; k0 += 8) {
        uint32_t a[4][4], b[4][2];
        #pragma unroll
        for (int mi = 0; mi < 4; mi++) {
            const uint32_t* p = &Qs[(wr + mi * 16 + g) * QKPAD + k0 + t];
            a[mi][0] = p[0]; a[mi][1] = p[8 * QKPAD]; a[mi][2] = p[4]; a[mi][3] = p[8 * QKPAD + 4];
        }
        #pragma unroll
        for (int ni = 0; ni < 4; ni++) {
            const uint32_t* p = &Ks[(wc + ni * 8 + g) * QKPAD + k0 + t];
            b[ni][0] = p[0]; b[ni][1] = p[4];
        }
        #pragma unroll
        for (int mi = 0; mi < 4; mi++)
            #pragma unroll
            for (int ni = 0; ni < 4; ni++)
                mma8(acc[mi][ni], a[mi], b[ni]);
    }

    size_t base = (size_t)bh * LL * SS;
    #pragma unroll
    for (int mi = 0; mi < 4; mi++) {
        int r0 = l0 + wr + mi * 16 + g;
        #pragma unroll
        for (int ni = 0; ni < 4; ni++) {
            int c = s0 + wc + ni * 8 + 2 * t;
            *(float2*)&g_scores[base + (size_t)r0 * SS + c] = make_float2(acc[mi][ni][0], acc[mi][ni][1]);
            *(float2*)&g_scores[base + (size_t)(r0 + 8) * SS + c] = make_float2(acc[mi][ni][2], acc[mi][ni][3]);
        }
    }

    // ---- epilogue: per-row partial (sum, sumsq) over this 128-col tile ----
    __syncthreads();                       // done reading Qs/Ks; reuse smem
    float2* spart = (float2*)shqk;         // [128 rows][4 wc-groups]
    #pragma unroll
    for (int mi = 0; mi < 4; mi++) {
        float s0v = 0.f, q0v = 0.f, s1v = 0.f, q1v = 0.f;
        #pragma unroll
        for (int ni = 0; ni < 4; ni++) {
            s0v += acc[mi][ni][0] + acc[mi][ni][1];
            q0v += acc[mi][ni][0] * acc[mi][ni][0] + acc[mi][ni][1] * acc[mi][ni][1];
            s1v += acc[mi][ni][2] + acc[mi][ni][3];
            q1v += acc[mi][ni][2] * acc[mi][ni][2] + acc[mi][ni][3] * acc[mi][ni][3];
        }
        #pragma unroll
        for (int o = 1; o <= 2; o <<= 1) {   // quad reduce over t
            s0v += __shfl_xor_sync(0xffffffffu, s0v, o);
            q0v += __shfl_xor_sync(0xffffffffu, q0v, o);
            s1v += __shfl_xor_sync(0xffffffffu, s1v, o);
            q1v += __shfl_xor_sync(0xffffffffu, q1v, o);
        }
        if (t == 0) {
            int rl = wr + mi * 16 + g;
            spart[rl * 4 + (wid & 3)] = make_float2(s0v, q0v);
            spart[(rl + 8) * 4 + (wid & 3)] = make_float2(s1v, q1v);
        }
    }
    __syncthreads();
    if (tid < 128) {
        float S = 0.f, Qq = 0.f;
        #pragma unroll
        for (int wcg = 0; wcg < 4; wcg++) {
            float2 v = spart[tid * 4 + wcg];
            S += v.x; Qq += v.y;
        }
        g_pstat[((size_t)bh * LL + l0 + tid) * NSTILE + blockIdx.x] = make_float2(S, Qq);
    }
}

// ==================== kernel 3: per-row alpha/shift from partials ====================
__global__ void __launch_bounds__(256) k_alpha() {
    int row = blockIdx.x * 256 + threadIdx.x;
    const float2* ps = g_pstat + (size_t)row * NSTILE;
    float S = 0.f, Q = 0.f;
    #pragma unroll
    for (int i = 0; i < NSTILE; i++) { float2 v = ps[i]; S += v.x; Q += v.y; }
    float mean = S * (1.0f / (float)SS);
    float var = (Q - S * mean) * (1.0f / (float)(SS - 1));   // unbiased
    float tau = sqrtf(fmaxf(var, 0.f) + EPSF);
    float alpha = SCALEF / tau;
    g_alsh[row] = make_float2(alpha, alpha * mean);
}

// ==================== kernel 4: out = (softmax(A) @ V)  fused, tf32 mma, 3-stage cp.async ====================
#define APAD 36    // 32+4: A [row][k] fragment reads conflict-free
#define VPAD 72    // 64+8: V [k][d] fragment reads conflict-free
#define NST 3
#define AST (128 * APAD)
#define VST (32 * VPAD)
#define AVSMEM ((NST * AST + NST * VST) * 4)   // 82944 B

__global__ void __launch_bounds__(256, 2) k_gemm_av(const float* __restrict__ V, float* __restrict__ O) {
    extern __shared__ uint32_t shav[];
    uint32_t* As = shav;                 // [NST][AST]
    uint32_t* Vs = shav + NST * AST;     // [NST][VST]
    __shared__ float sesum[128];
    int l0 = blockIdx.x << 7;
    int bh = blockIdx.y;
    int b = bh >> 3, h = bh & 7;
    const float* Vb = V + (size_t)b * SS * HE + h * EE;
    const float* Ar = g_scores + (size_t)bh * LL * SS + (size_t)l0 * SS;
    int tid = threadIdx.x;

    int afr = tid >> 3, afc = (tid & 7) * 4;     // A fill: 32 rows/pass × 4 passes
    int vfr = tid >> 4, vfc = (tid & 15) * 4;    // V fill: 16 rows/pass × 2 passes
    uint32_t asb = (uint32_t)__cvta_generic_to_shared(As);
    uint32_t vsb = (uint32_t)__cvta_generic_to_shared(Vs);

    int lane = tid & 31, wid = tid >> 5;
    int wr = (wid & 3) * 32;        // 4 row-groups of warps
    int wc = (wid >> 2) * 32;       // 2 col-groups of warps
    int g = lane >> 2, t4 = lane & 3;
    bool esum_warp = (wid >> 2) == 0;   // wc group 0 accumulates expsum

    // per-thread row constants: rows (wr + mi*16 + g) and (+8), mi = 0,1
    float al[2][2], sh[2][2];
    #pragma unroll
    for (int mi = 0; mi < 2; mi++) {
        float2 v0 = g_alsh[(size_t)bh * LL + l0 + wr + mi * 16 + g];
        float2 v1 = g_alsh[(size_t)bh * LL + l0 + wr + mi * 16 + g + 8];
        al[mi][0] = v0.x; sh[mi][0] = v0.y;
        al[mi][1] = v1.x; sh[mi][1] = v1.y;
    }

    float acc[2][4][4];
    #pragma unroll
    for (int i = 0; i < 2; i++)
        #pragma unroll
        for (int j = 0; j < 4; j++)
            #pragma unroll
            for (int r = 0; r < 4; r++) acc[i][j][r] = 0.f;
    float esum[2][2] = {};

    #define ISSUE(tt, buf)                                                              \
        do {                                                                            \
            const float* asrc = Ar + (tt) * 32;                                         \
            _Pragma("unroll")                                                           \
            for (int pp = 0; pp < 4; pp++) {                                            \
                int r = afr + pp * 32;                                                  \
                cpasync16(asb + (uint32_t)((buf) * AST + r * APAD + afc) * 4,           \
                          asrc + (size_t)r * SS + afc);                                 \
            }                                                                           \
            const float* vsrc = Vb + (size_t)((tt) * 32) * HE;                          \
            _Pragma("unroll")                                                           \
            for (int pp = 0; pp < 2; pp++) {                                            \
                int r = vfr + pp * 16;                                                  \
                cpasync16(vsb + (uint32_t)((buf) * VST + r * VPAD + vfc) * 4,           \
                          vsrc + (size_t)r * HE + vfc);                                 \
            }                                                                           \
        } while (0)

    ISSUE(0, 0); cp_commit();
    ISSUE(1, 1); cp_commit();

    for (int tt = 0; tt < 64; tt++) {
        int buf = tt % NST;
        if (tt + 2 < 64) { ISSUE(tt + 2, (tt + 2) % NST); cp_commit(); cp_wait<2>(); }
        else if (tt + 1 < 64) { cp_wait<1>(); }
        else { cp_wait<0>(); }
        __syncthreads();

        const uint32_t* Ab = As + buf * AST;
        const uint32_t* Vf = Vs + buf * VST;
        #pragma unroll
        for (int k0 = 0; k0 < 32; k0 += 8) {
            uint32_t a[2][4], bf[4][2];
            #pragma unroll
            for (int mi = 0; mi < 2; mi++) {
                const uint32_t* p = &Ab[(wr + mi * 16 + g) * APAD + k0 + t4];
                float e0 = __expf(fmaf(al[mi][0], __uint_as_float(p[0]), -sh[mi][0]));
                float e1 = __expf(fmaf(al[mi][1], __uint_as_float(p[8 * APAD]), -sh[mi][1]));
                float e2 = __expf(fmaf(al[mi][0], __uint_as_float(p[4]), -sh[mi][0]));
                float e3 = __expf(fmaf(al[mi][1], __uint_as_float(p[8 * APAD + 4]), -sh[mi][1]));
                if (esum_warp) {
                    esum[mi][0] += e0 + e2;
                    esum[mi][1] += e1 + e3;
                }
                a[mi][0] = f2tf(e0); a[mi][1] = f2tf(e1); a[mi][2] = f2tf(e2); a[mi][3] = f2tf(e3);
            }
            #pragma unroll
            for (int ni = 0; ni < 4; ni++) {
                bf[ni][0] = Vf[(k0 + t4) * VPAD + wc + ni * 8 + g];
                bf[ni][1] = Vf[(k0 + t4 + 4) * VPAD + wc + ni * 8 + g];
            }
            #pragma unroll
            for (int mi = 0; mi < 2; mi++)
                #pragma unroll
                for (int ni = 0; ni < 4; ni++)
                    mma8(acc[mi][ni], a[mi], bf[ni]);
        }
        __syncthreads();
    }

    // expsum: quad-reduce over t4 lanes, wc0 warps own rows wr..wr+31
    if (esum_warp) {
        #pragma unroll
        for (int mi = 0; mi < 2; mi++)
            #pragma unroll
            for (int hf = 0; hf < 2; hf++) {
                float v = esum[mi][hf];
                v += __shfl_xor_sync(0xffffffffu, v, 1);
                v += __shfl_xor_sync(0xffffffffu, v, 2);
                if (t4 == 0) sesum[wr + mi * 16 + g + hf * 8] = v;
            }
    }
    __syncthreads();

    #pragma unroll
    for (int mi = 0; mi < 2; mi++) {
        int r = wr + mi * 16 + g;
        float inv0 = 1.0f / sesum[r];
        float inv1 = 1.0f / sesum[r + 8];
        int rg = l0 + r;
        #pragma unroll
        for (int ni = 0; ni < 4; ni++) {
            int d = wc + ni * 8 + 2 * t4;
            size_t o0 = ((size_t)((size_t)b * LL + rg) * HH + h) * EE + d;
            *(float2*)&O[o0] = make_float2(acc[mi][ni][0] * inv0, acc[mi][ni][1] * inv0);
            size_t o1 = ((size_t)((size_t)b * LL + rg + 8) * HH + h) * EE + d;
            *(float2*)&O[o1] = make_float2(acc[mi][ni][2] * inv1, acc[mi][ni][3] * inv1);
        }
    }
}

// ==================== launch ====================
extern "C" void kernel_launch(void* const* d_in, const int* in_sizes, int n_in,
                              void* d_out, int out_size) {
    const float* q  = (const float*)d_in[0];
    const float* k  = (const float*)d_in[1];
    const float* v  = (const float*)d_in[2];
    const float* dw = (const float*)d_in[4];
    const float* dp = (const float*)d_in[5];
    float* out = (float*)d_out;

    const int qk_smem = 2 * 128 * QKPAD * 4;   // 69632 B
    cudaFuncSetAttribute(k_gemm_qk, cudaFuncAttributeMaxDynamicSharedMemorySize, qk_smem);
    cudaFuncSetAttribute(k_gemm_av, cudaFuncAttributeMaxDynamicSharedMemorySize, AVSMEM);

    k_transform<<<dim3(BB * LL, 2), 512>>>(q, k, dw, dp);
    k_gemm_qk  <<<dim3(SS / 128, LL / 128, BH), 256, qk_smem>>>();
    k_alpha    <<<NROWS / 256, 256>>>();
    k_gemm_av  <<<dim3(LL / 128, BH), 256, AVSMEM>>>(v, out);
}

// round 9
// speedup vs baseline: 4.4093x; 1.3674x over previous
#include <cuda_runtime.h>
#include <math.h>
#include <stdint.h>

#define BB 4
#define LL 2048
#define SS 2048
#define HH 8
#define EE 64
#define HE 512          // HH*EE
#define BH 32           // BB*HH
#define NELEM (BB*LL*HH*EE)
#define NROWS (BH * LL)      // 65536 attention rows
#define NSTILE 16            // SS/128 score tiles per row
#define EPSF 1e-6f
#define SCALEF 0.125f   // 1/sqrt(64)

// -------- device scratch (alloc-free rule: __device__ globals) --------
__device__ float g_qt[NELEM];       // tf32-rounded transformed Q
__device__ float g_kt[NELEM];       // tf32-rounded transformed K
__device__ float g_scores[(size_t)BH * LL * SS];   // 512 MB, raw fp32 scores
__device__ float2 g_pstat[(size_t)NROWS * NSTILE]; // per (row, s-tile): (sum, sumsq)
__device__ float2 g_alsh[NROWS];                   // per row: (alpha, shift)

__device__ __forceinline__ uint32_t f2tf(float f) {
    uint32_t r;
    asm("cvt.rna.tf32.f32 %0, %1;" : "=r"(r) : "f"(f));
    return r;
}

__device__ __forceinline__ void mma8(float* c, const uint32_t* a, const uint32_t* b) {
    asm volatile("mma.sync.aligned.m16n8k8.row.col.f32.tf32.tf32.f32 "
                 "{%0,%1,%2,%3},{%4,%5,%6,%7},{%8,%9},{%0,%1,%2,%3};"
                 : "+f"(c[0]), "+f"(c[1]), "+f"(c[2]), "+f"(c[3])
                 : "r"(a[0]), "r"(a[1]), "r"(a[2]), "r"(a[3]), "r"(b[0]), "r"(b[1]));
}

__device__ __forceinline__ void cpasync16(uint32_t dst, const void* src) {
    asm volatile("cp.async.cg.shared.global [%0], [%1], 16;" :: "r"(dst), "l"(src));
}
__device__ __forceinline__ void cp_commit() { asm volatile("cp.async.commit_group;"); }
template<int N> __device__ __forceinline__ void cp_wait() {
    asm volatile("cp.async.wait_group %0;" :: "n"(N));
}

// ==================== kernel 1: transform; std over HEADS (axis=-2), tf32-rounded out ====================
__global__ void __launch_bounds__(512) k_transform(const float* __restrict__ q,
                                                   const float* __restrict__ k,
                                                   const float* __restrict__ dw,
                                                   const float* __restrict__ dp) {
    int sel = blockIdx.y;
    const float* x = (sel ? k : q) + (size_t)blockIdx.x * HE;
    float* o = (sel ? g_kt : g_qt) + (size_t)blockIdx.x * HE;
    float w = dw[0];
    float p = dp[0];
    int tid = threadIdx.x;          // h*64 + e
    int e = tid & 63;
    float v = x[tid];

    __shared__ float s1[512];
    __shared__ float istd[64];
    s1[tid] = v;
    __syncthreads();
    if (tid < 64) {
        float s = 0.f, ss = 0.f;
        #pragma unroll
        for (int h = 0; h < 8; h++) {
            float u = s1[h * 64 + tid];
            s += u; ss += u * u;
        }
        float mean = s * 0.125f;
        float var = (ss - s * mean) * (1.0f / 7.0f);    // unbiased n=8
        istd[tid] = 1.0f / (sqrtf(fmaxf(var, 0.f)) + EPSF);
    }
    __syncthreads();
    o[tid] = __uint_as_float(f2tf(tanhf(v * istd[e] * w) * p));
}

// ==================== kernel 2: scores = qt @ kt^T (tf32 mma, cp.async 2-chunk) + row stats ====================
#define QKPAD 36
#define QKST (128 * QKPAD)
#define QKSMEM (4 * QKST * 4)    // 2 bufs x (Q+K) = 73728 B

__global__ void __launch_bounds__(256, 2) k_gemm_qk() {
    extern __shared__ uint32_t shqk[];
    uint32_t* Qs = shqk;                 // [2][QKST]
    uint32_t* Ks = shqk + 2 * QKST;      // [2][QKST]
    int bh = blockIdx.z;
    int l0 = blockIdx.y << 7, s0 = blockIdx.x << 7;
    const float* Q = g_qt + (size_t)(bh >> 3) * LL * HE + (bh & 7) * EE;
    const float* K = g_kt + (size_t)(bh >> 3) * LL * HE + (bh & 7) * EE;
    int tid = threadIdx.x;

    int afr = tid >> 3, afc = (tid & 7) * 4;   // 32 rows/pass, 32 cols per chunk
    uint32_t qsb = (uint32_t)__cvta_generic_to_shared(Qs);
    uint32_t ksb = (uint32_t)__cvta_generic_to_shared(Ks);

#define ISSUEQK(kc, buf)                                                            \
    do {                                                                            \
        _Pragma("unroll")                                                           \
        for (int pp = 0; pp < 4; pp++) {                                            \
            int r = afr + pp * 32;                                                  \
            cpasync16(qsb + (uint32_t)((buf) * QKST + r * QKPAD + afc) * 4,         \
                      Q + (size_t)(l0 + r) * HE + (kc) * 32 + afc);                 \
            cpasync16(ksb + (uint32_t)((buf) * QKST + r * QKPAD + afc) * 4,         \
                      K + (size_t)(s0 + r) * HE + (kc) * 32 + afc);                 \
        }                                                                           \
    } while (0)

    ISSUEQK(0, 0); cp_commit();
    ISSUEQK(1, 1); cp_commit();
#undef ISSUEQK

    int lane = tid & 31, wid = tid >> 5;
    int wr = (wid >> 2) * 64;     // warp row base (2 groups)
    int wc = (wid & 3) * 32;      // warp col base (4 groups)
    int g = lane >> 2, t = lane & 3;

    float acc[4][4][4];
    #pragma unroll
    for (int i = 0; i < 4; i++)
        #pragma unroll
        for (int j = 0; j < 4; j++)
            #pragma unroll
            for (int r = 0; r < 4; r++) acc[i][j][r] = 0.f;

    #pragma unroll
    for (int kc = 0; kc < 2; kc++) {
        if (kc == 0) cp_wait<1>(); else cp_wait<0>();
        __syncthreads();
        const uint32_t* Qb = Qs + kc * QKST;
        const uint32_t* Kb = Ks + kc * QKST;
        #pragma unroll
        for (int k0 = 0; k0 < 32; k0 += 8) {
            uint32_t a[4][4], b[4][2];
            #pragma unroll
            for (int mi = 0; mi < 4; mi++) {
                const uint32_t* p = &Qb[(wr + mi * 16 + g) * QKPAD + k0 + t];
                a[mi][0] = p[0]; a[mi][1] = p[8 * QKPAD]; a[mi][2] = p[4]; a[mi][3] = p[8 * QKPAD + 4];
            }
            #pragma unroll
            for (int ni = 0; ni < 4; ni++) {
                const uint32_t* p = &Kb[(wc + ni * 8 + g) * QKPAD + k0 + t];
                b[ni][0] = p[0]; b[ni][1] = p[4];
            }
            #pragma unroll
            for (int mi = 0; mi < 4; mi++)
                #pragma unroll
                for (int ni = 0; ni < 4; ni++)
                    mma8(acc[mi][ni], a[mi], b[ni]);
        }
        if (kc == 0) __syncthreads();
    }

    size_t base = (size_t)bh * LL * SS;
    #pragma unroll
    for (int mi = 0; mi < 4; mi++) {
        int r0 = l0 + wr + mi * 16 + g;
        #pragma unroll
        for (int ni = 0; ni < 4; ni++) {
            int c = s0 + wc + ni * 8 + 2 * t;
            *(float2*)&g_scores[base + (size_t)r0 * SS + c] = make_float2(acc[mi][ni][0], acc[mi][ni][1]);
            *(float2*)&g_scores[base + (size_t)(r0 + 8) * SS + c] = make_float2(acc[mi][ni][2], acc[mi][ni][3]);
        }
    }

    // ---- epilogue: per-row partial (sum, sumsq) over this 128-col tile ----
    __syncthreads();                       // done with Qs/Ks; reuse smem
    float2* spart = (float2*)shqk;         // [128 rows][4 wc-groups]
    #pragma unroll
    for (int mi = 0; mi < 4; mi++) {
        float s0v = 0.f, q0v = 0.f, s1v = 0.f, q1v = 0.f;
        #pragma unroll
        for (int ni = 0; ni < 4; ni++) {
            s0v += acc[mi][ni][0] + acc[mi][ni][1];
            q0v += acc[mi][ni][0] * acc[mi][ni][0] + acc[mi][ni][1] * acc[mi][ni][1];
            s1v += acc[mi][ni][2] + acc[mi][ni][3];
            q1v += acc[mi][ni][2] * acc[mi][ni][2] + acc[mi][ni][3] * acc[mi][ni][3];
        }
        #pragma unroll
        for (int o = 1; o <= 2; o <<= 1) {
            s0v += __shfl_xor_sync(0xffffffffu, s0v, o);
            q0v += __shfl_xor_sync(0xffffffffu, q0v, o);
            s1v += __shfl_xor_sync(0xffffffffu, s1v, o);
            q1v += __shfl_xor_sync(0xffffffffu, q1v, o);
        }
        if (t == 0) {
            int rl = wr + mi * 16 + g;
            spart[rl * 4 + (wid & 3)] = make_float2(s0v, q0v);
            spart[(rl + 8) * 4 + (wid & 3)] = make_float2(s1v, q1v);
        }
    }
    __syncthreads();
    if (tid < 128) {
        float S = 0.f, Qq = 0.f;
        #pragma unroll
        for (int wcg = 0; wcg < 4; wcg++) {
            float2 v = spart[tid * 4 + wcg];
            S += v.x; Qq += v.y;
        }
        g_pstat[((size_t)bh * LL + l0 + tid) * NSTILE + blockIdx.x] = make_float2(S, Qq);
    }
}

// ==================== kernel 3: per-row alpha/shift from partials ====================
__global__ void __launch_bounds__(256) k_alpha() {
    int row = blockIdx.x * 256 + threadIdx.x;
    const float2* ps = g_pstat + (size_t)row * NSTILE;
    float S = 0.f, Q = 0.f;
    #pragma unroll
    for (int i = 0; i < NSTILE; i++) { float2 v = ps[i]; S += v.x; Q += v.y; }
    float mean = S * (1.0f / (float)SS);
    float var = (Q - S * mean) * (1.0f / (float)(SS - 1));   // unbiased
    float tau = sqrtf(fmaxf(var, 0.f) + EPSF);
    float alpha = SCALEF / tau;
    g_alsh[row] = make_float2(alpha, alpha * mean);
}

// ==================== kernel 4: out = softmax(A) @ V  fused, 8x1 warp layout, 3-stage cp.async ====================
#define APAD 36    // A [row][k] fragment reads conflict-free
#define VPAD 72    // V [k][d] fragment reads conflict-free
#define NST 3
#define AST (128 * APAD)
#define VST (32 * VPAD)
#define AVSMEM ((NST * AST + NST * VST) * 4)   // 82944 B

__global__ void __launch_bounds__(256, 2) k_gemm_av(const float* __restrict__ V, float* __restrict__ O) {
    extern __shared__ uint32_t shav[];
    uint32_t* As = shav;                 // [NST][AST]
    uint32_t* Vs = shav + NST * AST;     // [NST][VST]
    int l0 = blockIdx.x << 7;
    int bh = blockIdx.y;
    int b = bh >> 3, h = bh & 7;
    const float* Vb = V + (size_t)b * SS * HE + h * EE;
    const float* Ar = g_scores + (size_t)bh * LL * SS + (size_t)l0 * SS;
    int tid = threadIdx.x;

    int afr = tid >> 3, afc = (tid & 7) * 4;     // A fill: 32 rows/pass x 4 passes
    int vfr = tid >> 4, vfc = (tid & 15) * 4;    // V fill: 16 rows/pass x 2 passes
    uint32_t asb = (uint32_t)__cvta_generic_to_shared(As);
    uint32_t vsb = (uint32_t)__cvta_generic_to_shared(Vs);

    int lane = tid & 31, wid = tid >> 5;
    int wr = wid * 16;               // each warp owns a unique 16-row strip, all 64 cols
    int g = lane >> 2, t4 = lane & 3;

    // per-thread row constants: rows wr+g and wr+8+g
    float2 v0 = g_alsh[(size_t)bh * LL + l0 + wr + g];
    float2 v1 = g_alsh[(size_t)bh * LL + l0 + wr + g + 8];
    float al0 = v0.x, sh0 = v0.y, al1 = v1.x, sh1 = v1.y;

    float acc[8][4];
    #pragma unroll
    for (int j = 0; j < 8; j++)
        #pragma unroll
        for (int r = 0; r < 4; r++) acc[j][r] = 0.f;
    float esum0 = 0.f, esum1 = 0.f;

#define ISSUEAV(tt, buf)                                                            \
    do {                                                                            \
        const float* asrc = Ar + (tt) * 32;                                         \
        _Pragma("unroll")                                                           \
        for (int pp = 0; pp < 4; pp++) {                                            \
            int r = afr + pp * 32;                                                  \
            cpasync16(asb + (uint32_t)((buf) * AST + r * APAD + afc) * 4,           \
                      asrc + (size_t)r * SS + afc);                                 \
        }                                                                           \
        const float* vsrc = Vb + (size_t)((tt) * 32) * HE;                          \
        _Pragma("unroll")                                                           \
        for (int pp = 0; pp < 2; pp++) {                                            \
            int r = vfr + pp * 16;                                                  \
            cpasync16(vsb + (uint32_t)((buf) * VST + r * VPAD + vfc) * 4,           \
                      vsrc + (size_t)r * HE + vfc);                                 \
        }                                                                           \
    } while (0)

    ISSUEAV(0, 0); cp_commit();
    ISSUEAV(1, 1); cp_commit();

    for (int tt = 0; tt < 64; tt++) {
        int buf = tt % NST;
        if (tt + 2 < 64) { ISSUEAV(tt + 2, (tt + 2) % NST); cp_commit(); cp_wait<2>(); }
        else if (tt + 1 < 64) { cp_wait<1>(); }
        else { cp_wait<0>(); }
        __syncthreads();

        const uint32_t* Ab = As + buf * AST;
        const uint32_t* Vf = Vs + buf * VST;
        #pragma unroll
        for (int k0 = 0; k0 < 32; k0 += 8) {
            uint32_t a[4], bf[8][2];
            {
                const uint32_t* p = &Ab[(wr + g) * APAD + k0 + t4];
                float e0 = __expf(fmaf(al0, __uint_as_float(p[0]), -sh0));
                float e1 = __expf(fmaf(al1, __uint_as_float(p[8 * APAD]), -sh1));
                float e2 = __expf(fmaf(al0, __uint_as_float(p[4]), -sh0));
                float e3 = __expf(fmaf(al1, __uint_as_float(p[8 * APAD + 4]), -sh1));
                esum0 += e0 + e2;
                esum1 += e1 + e3;
                a[0] = f2tf(e0); a[1] = f2tf(e1); a[2] = f2tf(e2); a[3] = f2tf(e3);
            }
            #pragma unroll
            for (int ni = 0; ni < 8; ni++) {
                bf[ni][0] = Vf[(k0 + t4) * VPAD + ni * 8 + g];
                bf[ni][1] = Vf[(k0 + t4 + 4) * VPAD + ni * 8 + g];
            }
            #pragma unroll
            for (int ni = 0; ni < 8; ni++)
                mma8(acc[ni], a, bf[ni]);
        }
        __syncthreads();
    }
#undef ISSUEAV

    // expsum: butterfly over the t4 quad -> every lane holds the row total
    esum0 += __shfl_xor_sync(0xffffffffu, esum0, 1);
    esum0 += __shfl_xor_sync(0xffffffffu, esum0, 2);
    esum1 += __shfl_xor_sync(0xffffffffu, esum1, 1);
    esum1 += __shfl_xor_sync(0xffffffffu, esum1, 2);
    float inv0 = 1.0f / esum0;
    float inv1 = 1.0f / esum1;

    int r0 = l0 + wr + g;
    #pragma unroll
    for (int ni = 0; ni < 8; ni++) {
        int d = ni * 8 + 2 * t4;
        size_t o0 = ((size_t)((size_t)b * LL + r0) * HH + h) * EE + d;
        *(float2*)&O[o0] = make_float2(acc[ni][0] * inv0, acc[ni][1] * inv0);
        size_t o1 = ((size_t)((size_t)b * LL + r0 + 8) * HH + h) * EE + d;
        *(float2*)&O[o1] = make_float2(acc[ni][2] * inv1, acc[ni][3] * inv1);
    }
}

// ==================== launch ====================
extern "C" void kernel_launch(void* const* d_in, const int* in_sizes, int n_in,
                              void* d_out, int out_size) {
    const float* q  = (const float*)d_in[0];
    const float* k  = (const float*)d_in[1];
    const float* v  = (const float*)d_in[2];
    const float* dw = (const float*)d_in[4];
    const float* dp = (const float*)d_in[5];
    float* out = (float*)d_out;

    cudaFuncSetAttribute(k_gemm_qk, cudaFuncAttributeMaxDynamicSharedMemorySize, QKSMEM);
    cudaFuncSetAttribute(k_gemm_av, cudaFuncAttributeMaxDynamicSharedMemorySize, AVSMEM);

    k_transform<<<dim3(BB * LL, 2), 512>>>(q, k, dw, dp);
    k_gemm_qk  <<<dim3(SS / 128, LL / 128, BH), 256, QKSMEM>>>();
    k_alpha    <<<NROWS / 256, 256>>>();
    k_gemm_av  <<<dim3(LL / 128, BH), 256, AVSMEM>>>(v, out);
}

// round 11
// speedup vs baseline: 4.6395x; 1.0522x over previous
#include <cuda_runtime.h>
#include <cuda_fp16.h>
#include <math.h>
#include <stdint.h>

#define BB 4
#define LL 2048
#define SS 2048
#define HH 8
#define EE 64
#define HE 512          // HH*EE
#define BH 32           // BB*HH
#define NELEM (BB*LL*HH*EE)
#define NROWS (BH * LL)      // 65536 attention rows
#define NSTILE 16            // SS/128 score tiles per row
#define EPSF 1e-6f
#define SCALEF 0.125f   // 1/sqrt(64)

// -------- device scratch (alloc-free rule: __device__ globals) --------
__device__ float g_qt[NELEM];       // tf32-rounded transformed Q
__device__ float g_kt[NELEM];       // tf32-rounded transformed K
__device__ __half g_scores[(size_t)BH * LL * SS];  // 256 MB, fp16 scores
__device__ float2 g_pstat[(size_t)NROWS * NSTILE]; // per (row, s-tile): (sum, sumsq)
__device__ float2 g_alsh[NROWS];                   // per row: (alpha, shift)

__device__ __forceinline__ uint32_t f2tf(float f) {
    uint32_t r;
    asm("cvt.rna.tf32.f32 %0, %1;" : "=r"(r) : "f"(f));
    return r;
}

__device__ __forceinline__ void mma8(float* c, const uint32_t* a, const uint32_t* b) {
    asm volatile("mma.sync.aligned.m16n8k8.row.col.f32.tf32.tf32.f32 "
                 "{%0,%1,%2,%3},{%4,%5,%6,%7},{%8,%9},{%0,%1,%2,%3};"
                 : "+f"(c[0]), "+f"(c[1]), "+f"(c[2]), "+f"(c[3])
                 : "r"(a[0]), "r"(a[1]), "r"(a[2]), "r"(a[3]), "r"(b[0]), "r"(b[1]));
}

__device__ __forceinline__ void cpasync16(uint32_t dst, const void* src) {
    asm volatile("cp.async.cg.shared.global [%0], [%1], 16;" :: "r"(dst), "l"(src));
}
__device__ __forceinline__ void cp_commit() { asm volatile("cp.async.commit_group;"); }
template<int N> __device__ __forceinline__ void cp_wait() {
    asm volatile("cp.async.wait_group %0;" :: "n"(N));
}

// ==================== kernel 1: transform; std over HEADS (axis=-2), tf32-rounded out ====================
__global__ void __launch_bounds__(512) k_transform(const float* __restrict__ q,
                                                   const float* __restrict__ k,
                                                   const float* __restrict__ dw,
                                                   const float* __restrict__ dp) {
    int sel = blockIdx.y;
    const float* x = (sel ? k : q) + (size_t)blockIdx.x * HE;
    float* o = (sel ? g_kt : g_qt) + (size_t)blockIdx.x * HE;
    float w = dw[0];
    float p = dp[0];
    int tid = threadIdx.x;          // h*64 + e
    int e = tid & 63;
    float v = x[tid];

    __shared__ float s1[512];
    __shared__ float istd[64];
    s1[tid] = v;
    __syncthreads();
    if (tid < 64) {
        float s = 0.f, ss = 0.f;
        #pragma unroll
        for (int h = 0; h < 8; h++) {
            float u = s1[h * 64 + tid];
            s += u; ss += u * u;
        }
        float mean = s * 0.125f;
        float var = (ss - s * mean) * (1.0f / 7.0f);    // unbiased n=8
        istd[tid] = 1.0f / (sqrtf(fmaxf(var, 0.f)) + EPSF);
    }
    __syncthreads();
    o[tid] = __uint_as_float(f2tf(tanhf(v * istd[e] * w) * p));
}

// ==================== kernel 2: scores = qt @ kt^T (tf32 mma, cp.async) -> fp16 + row stats ====================
#define QKPAD 36
#define QKST (128 * QKPAD)
#define QKSMEM (4 * QKST * 4)    // 73728 B

__global__ void __launch_bounds__(256, 2) k_gemm_qk() {
    extern __shared__ uint32_t shqk[];
    uint32_t* Qs = shqk;                 // [2][QKST]
    uint32_t* Ks = shqk + 2 * QKST;      // [2][QKST]
    int bh = blockIdx.z;
    int l0 = blockIdx.y << 7, s0 = blockIdx.x << 7;
    const float* Q = g_qt + (size_t)(bh >> 3) * LL * HE + (bh & 7) * EE;
    const float* K = g_kt + (size_t)(bh >> 3) * LL * HE + (bh & 7) * EE;
    int tid = threadIdx.x;

    int afr = tid >> 3, afc = (tid & 7) * 4;   // 32 rows/pass, 32 cols per chunk
    uint32_t qsb = (uint32_t)__cvta_generic_to_shared(Qs);
    uint32_t ksb = (uint32_t)__cvta_generic_to_shared(Ks);

#define ISSUEQK(kc, buf)                                                            \
    do {                                                                            \
        _Pragma("unroll")                                                           \
        for (int pp = 0; pp < 4; pp++) {                                            \
            int r = afr + pp * 32;                                                  \
            cpasync16(qsb + (uint32_t)((buf) * QKST + r * QKPAD + afc) * 4,         \
                      Q + (size_t)(l0 + r) * HE + (kc) * 32 + afc);                 \
            cpasync16(ksb + (uint32_t)((buf) * QKST + r * QKPAD + afc) * 4,         \
                      K + (size_t)(s0 + r) * HE + (kc) * 32 + afc);                 \
        }                                                                           \
    } while (0)

    ISSUEQK(0, 0); cp_commit();
    ISSUEQK(1, 1); cp_commit();
#undef ISSUEQK

    int lane = tid & 31, wid = tid >> 5;
    int wr = (wid >> 2) * 64;     // warp row base (2 groups)
    int wc = (wid & 3) * 32;      // warp col base (4 groups)
    int g = lane >> 2, t = lane & 3;

    float acc[4][4][4];
    #pragma unroll
    for (int i = 0; i < 4; i++)
        #pragma unroll
        for (int j = 0; j < 4; j++)
            #pragma unroll
            for (int r = 0; r < 4; r++) acc[i][j][r] = 0.f;

    #pragma unroll
    for (int kc = 0; kc < 2; kc++) {
        if (kc == 0) cp_wait<1>(); else cp_wait<0>();
        __syncthreads();
        const uint32_t* Qb = Qs + kc * QKST;
        const uint32_t* Kb = Ks + kc * QKST;
        #pragma unroll
        for (int k0 = 0; k0 < 32; k0 += 8) {
            uint32_t a[4][4], b[4][2];
            #pragma unroll
            for (int mi = 0; mi < 4; mi++) {
                const uint32_t* p = &Qb[(wr + mi * 16 + g) * QKPAD + k0 + t];
                a[mi][0] = p[0]; a[mi][1] = p[8 * QKPAD]; a[mi][2] = p[4]; a[mi][3] = p[8 * QKPAD + 4];
            }
            #pragma unroll
            for (int ni = 0; ni < 4; ni++) {
                const uint32_t* p = &Kb[(wc + ni * 8 + g) * QKPAD + k0 + t];
                b[ni][0] = p[0]; b[ni][1] = p[4];
            }
            #pragma unroll
            for (int mi = 0; mi < 4; mi++)
                #pragma unroll
                for (int ni = 0; ni < 4; ni++)
                    mma8(acc[mi][ni], a[mi], b[ni]);
        }
        if (kc == 0) __syncthreads();
    }

    size_t base = (size_t)bh * LL * SS;
    #pragma unroll
    for (int mi = 0; mi < 4; mi++) {
        int r0 = l0 + wr + mi * 16 + g;
        #pragma unroll
        for (int ni = 0; ni < 4; ni++) {
            int c = s0 + wc + ni * 8 + 2 * t;
            *(__half2*)&g_scores[base + (size_t)r0 * SS + c] =
                __floats2half2_rn(acc[mi][ni][0], acc[mi][ni][1]);
            *(__half2*)&g_scores[base + (size_t)(r0 + 8) * SS + c] =
                __floats2half2_rn(acc[mi][ni][2], acc[mi][ni][3]);
        }
    }

    // ---- epilogue: per-row partial (sum, sumsq) over this 128-col tile (fp32 accs) ----
    __syncthreads();                       // done with Qs/Ks; reuse smem
    float2* spart = (float2*)shqk;         // [128 rows][4 wc-groups]
    #pragma unroll
    for (int mi = 0; mi < 4; mi++) {
        float s0v = 0.f, q0v = 0.f, s1v = 0.f, q1v = 0.f;
        #pragma unroll
        for (int ni = 0; ni < 4; ni++) {
            s0v += acc[mi][ni][0] + acc[mi][ni][1];
            q0v += acc[mi][ni][0] * acc[mi][ni][0] + acc[mi][ni][1] * acc[mi][ni][1];
            s1v += acc[mi][ni][2] + acc[mi][ni][3];
            q1v += acc[mi][ni][2] * acc[mi][ni][2] + acc[mi][ni][3] * acc[mi][ni][3];
        }
        #pragma unroll
        for (int o = 1; o <= 2; o <<= 1) {
            s0v += __shfl_xor_sync(0xffffffffu, s0v, o);
            q0v += __shfl_xor_sync(0xffffffffu, q0v, o);
            s1v += __shfl_xor_sync(0xffffffffu, s1v, o);
            q1v += __shfl_xor_sync(0xffffffffu, q1v, o);
        }
        if (t == 0) {
            int rl = wr + mi * 16 + g;
            spart[rl * 4 + (wid & 3)] = make_float2(s0v, q0v);
            spart[(rl + 8) * 4 + (wid & 3)] = make_float2(s1v, q1v);
        }
    }
    __syncthreads();
    if (tid < 128) {
        float S = 0.f, Qq = 0.f;
        #pragma unroll
        for (int wcg = 0; wcg < 4; wcg++) {
            float2 v = spart[tid * 4 + wcg];
            S += v.x; Qq += v.y;
        }
        g_pstat[((size_t)bh * LL + l0 + tid) * NSTILE + blockIdx.x] = make_float2(S, Qq);
    }
}

// ==================== kernel 3: per-row alpha/shift from partials ====================
__global__ void __launch_bounds__(256) k_alpha() {
    int row = blockIdx.x * 256 + threadIdx.x;
    const float2* ps = g_pstat + (size_t)row * NSTILE;
    float S = 0.f, Q = 0.f;
    #pragma unroll
    for (int i = 0; i < NSTILE; i++) { float2 v = ps[i]; S += v.x; Q += v.y; }
    float mean = S * (1.0f / (float)SS);
    float var = (Q - S * mean) * (1.0f / (float)(SS - 1));   // unbiased
    float tau = sqrtf(fmaxf(var, 0.f) + EPSF);
    float alpha = SCALEF / tau;
    g_alsh[row] = make_float2(alpha, alpha * mean);
}

// ==================== kernel 4: out = softmax(A) @ V  fused, fp16 scores, 3-stage cp.async ====================
#define APADH 40                       // halfs per A row (80 B): 16B-aligned rows + conflict-free reads
#define ASTB (128 * APADH * 2)         // 10240 B per A stage
#define VPAD 72                        // floats per V row
#define VSTB (32 * VPAD * 4)           // 9216 B per V stage
#define NST 3
#define AVSMEM (NST * (ASTB + VSTB))   // 58368 B

__global__ void __launch_bounds__(256, 2) k_gemm_av(const float* __restrict__ V, float* __restrict__ O) {
    extern __shared__ char shav[];
    char* Abase = shav;                  // [NST][ASTB]
    char* Vbase = shav + NST * ASTB;     // [NST][VSTB]
    int l0 = blockIdx.x << 7;
    int bh = blockIdx.y;
    int b = bh >> 3, h = bh & 7;
    const float* Vb = V + (size_t)b * SS * HE + h * EE;
    const __half* Ar = g_scores + (size_t)bh * LL * SS + (size_t)l0 * SS;
    int tid = threadIdx.x;

    int afr = tid >> 2, afc = (tid & 3) * 8;     // A fill: halfs; 64 rows/pass x 2 passes
    int vfr = tid >> 4, vfc = (tid & 15) * 4;    // V fill: floats; 16 rows/pass x 2 passes
    uint32_t asb = (uint32_t)__cvta_generic_to_shared(Abase);
    uint32_t vsb = (uint32_t)__cvta_generic_to_shared(Vbase);

    int lane = tid & 31, wid = tid >> 5;
    int wr = wid * 16;               // each warp owns a unique 16-row strip, all 64 cols
    int g = lane >> 2, t4 = lane & 3;

    // per-thread row constants: rows wr+g and wr+8+g
    float2 v0 = g_alsh[(size_t)bh * LL + l0 + wr + g];
    float2 v1 = g_alsh[(size_t)bh * LL + l0 + wr + g + 8];
    float al0 = v0.x, sh0 = v0.y, al1 = v1.x, sh1 = v1.y;

    float acc[8][4];
    #pragma unroll
    for (int j = 0; j < 8; j++)
        #pragma unroll
        for (int r = 0; r < 4; r++) acc[j][r] = 0.f;
    float esum0 = 0.f, esum1 = 0.f;

#define ISSUEAV(tt, buf)                                                            \
    do {                                                                            \
        const __half* asrc = Ar + (tt) * 32;                                        \
        _Pragma("unroll")                                                           \
        for (int pp = 0; pp < 2; pp++) {                                            \
            int r = afr + pp * 64;                                                  \
            cpasync16(asb + (uint32_t)((buf) * ASTB + (r * APADH + afc) * 2),       \
                      asrc + (size_t)r * SS + afc);                                 \
        }                                                                           \
        const float* vsrc = Vb + (size_t)((tt) * 32) * HE;                          \
        _Pragma("unroll")                                                           \
        for (int pp = 0; pp < 2; pp++) {                                            \
            int r = vfr + pp * 16;                                                  \
            cpasync16(vsb + (uint32_t)((buf) * VSTB + (r * VPAD + vfc) * 4),        \
                      vsrc + (size_t)r * HE + vfc);                                 \
        }                                                                           \
    } while (0)

    ISSUEAV(0, 0); cp_commit();
    ISSUEAV(1, 1); cp_commit();

    for (int tt = 0; tt < 64; tt++) {
        int buf = tt % NST;
        if (tt + 2 < 64) { ISSUEAV(tt + 2, (tt + 2) % NST); cp_commit(); cp_wait<2>(); }
        else if (tt + 1 < 64) { cp_wait<1>(); }
        else { cp_wait<0>(); }
        __syncthreads();

        const __half* Ab = (const __half*)(Abase + buf * ASTB);
        const uint32_t* Vf = (const uint32_t*)(Vbase + buf * VSTB);
        #pragma unroll
        for (int k0 = 0; k0 < 32; k0 += 8) {
            uint32_t a[4], bf[8][2];
            {
                const __half* pa = Ab + (wr + g) * APADH + k0 + t4;
                float e0 = __expf(fmaf(al0, __half2float(pa[0]), -sh0));
                float e1 = __expf(fmaf(al1, __half2float(pa[8 * APADH]), -sh1));
                float e2 = __expf(fmaf(al0, __half2float(pa[4]), -sh0));
                float e3 = __expf(fmaf(al1, __half2float(pa[8 * APADH + 4]), -sh1));
                esum0 += e0 + e2;
                esum1 += e1 + e3;
                a[0] = f2tf(e0); a[1] = f2tf(e1); a[2] = f2tf(e2); a[3] = f2tf(e3);
            }
            #pragma unroll
            for (int ni = 0; ni < 8; ni++) {
                bf[ni][0] = Vf[(k0 + t4) * VPAD + ni * 8 + g];
                bf[ni][1] = Vf[(k0 + t4 + 4) * VPAD + ni * 8 + g];
            }
            #pragma unroll
            for (int ni = 0; ni < 8; ni++)
                mma8(acc[ni], a, bf[ni]);
        }
        __syncthreads();
    }
#undef ISSUEAV

    // expsum: butterfly over the t4 quad -> every lane holds the row total
    esum0 += __shfl_xor_sync(0xffffffffu, esum0, 1);
    esum0 += __shfl_xor_sync(0xffffffffu, esum0, 2);
    esum1 += __shfl_xor_sync(0xffffffffu, esum1, 1);
    esum1 += __shfl_xor_sync(0xffffffffu, esum1, 2);
    float inv0 = 1.0f / esum0;
    float inv1 = 1.0f / esum1;

    int r0 = l0 + wr + g;
    #pragma unroll
    for (int ni = 0; ni < 8; ni++) {
        int d = ni * 8 + 2 * t4;
        size_t o0 = ((size_t)((size_t)b * LL + r0) * HH + h) * EE + d;
        *(float2*)&O[o0] = make_float2(acc[ni][0] * inv0, acc[ni][1] * inv0);
        size_t o1 = ((size_t)((size_t)b * LL + r0 + 8) * HH + h) * EE + d;
        *(float2*)&O[o1] = make_float2(acc[ni][2] * inv1, acc[ni][3] * inv1);
    }
}

// ==================== launch ====================
extern "C" void kernel_launch(void* const* d_in, const int* in_sizes, int n_in,
                              void* d_out, int out_size) {
    const float* q  = (const float*)d_in[0];
    const float* k  = (const float*)d_in[1];
    const float* v  = (const float*)d_in[2];
    const float* dw = (const float*)d_in[4];
    const float* dp = (const float*)d_in[5];
    float* out = (float*)d_out;

    cudaFuncSetAttribute(k_gemm_qk, cudaFuncAttributeMaxDynamicSharedMemorySize, QKSMEM);
    cudaFuncSetAttribute(k_gemm_av, cudaFuncAttributeMaxDynamicSharedMemorySize, AVSMEM);

    k_transform<<<dim3(BB * LL, 2), 512>>>(q, k, dw, dp);
    k_gemm_qk  <<<dim3(SS / 128, LL / 128, BH), 256, QKSMEM>>>();
    k_alpha    <<<NROWS / 256, 256>>>();
    k_gemm_av  <<<dim3(LL / 128, BH), 256, AVSMEM>>>(v, out);
}

// round 14
// speedup vs baseline: 5.2529x; 1.1322x over previous
#include <cuda_runtime.h>
#include <cuda_fp16.h>
#include <math.h>
#include <stdint.h>

#define BB 4
#define LL 2048
#define SS 2048
#define HH 8
#define EE 64
#define HE 512          // HH*EE
#define BH 32           // BB*HH
#define NELEM (BB*LL*HH*EE)
#define NROWS (BH * LL)      // 65536 attention rows
#define NSTILE 16            // SS/128 score tiles per row
#define EPSF 1e-6f
#define SCALEF 0.125f   // 1/sqrt(64)

// -------- device scratch (alloc-free rule: __device__ globals) --------
__device__ __half g_qth[NELEM];                    // fp16 transformed Q (8 MB)
__device__ __half g_kth[NELEM];                    // fp16 transformed K
__device__ __half g_vt[(size_t)BH * EE * SS];      // fp16 V transposed [bh][d][s] (8 MB)
__device__ __half g_scores[(size_t)BH * LL * SS];  // 256 MB fp16 scores
__device__ float2 g_pstat[(size_t)NROWS * NSTILE]; // per (row, s-tile): (sum, sumsq)
__device__ float2 g_alsh[NROWS];                   // per row: (alpha, shift)

__device__ __forceinline__ void mma16(float* c, const uint32_t* a, const uint32_t* b) {
    asm volatile("mma.sync.aligned.m16n8k16.row.col.f32.f16.f16.f32 "
                 "{%0,%1,%2,%3},{%4,%5,%6,%7},{%8,%9},{%0,%1,%2,%3};"
                 : "+f"(c[0]), "+f"(c[1]), "+f"(c[2]), "+f"(c[3])
                 : "r"(a[0]), "r"(a[1]), "r"(a[2]), "r"(a[3]), "r"(b[0]), "r"(b[1]));
}

__device__ __forceinline__ void cpasync16(uint32_t dst, const void* src) {
    asm volatile("cp.async.cg.shared.global [%0], [%1], 16;" :: "r"(dst), "l"(src));
}
__device__ __forceinline__ void cp_commit() { asm volatile("cp.async.commit_group;"); }
template<int N> __device__ __forceinline__ void cp_wait() {
    asm volatile("cp.async.wait_group %0;" :: "n"(N));
}
__device__ __forceinline__ uint32_t h2u(__half2 h) { return *reinterpret_cast<uint32_t*>(&h); }

// ==================== kernel 1: transform; std over HEADS (axis=-2), fp16 out ====================
__global__ void __launch_bounds__(512) k_transform(const float* __restrict__ q,
                                                   const float* __restrict__ k,
                                                   const float* __restrict__ dw,
                                                   const float* __restrict__ dp) {
    int sel = blockIdx.y;
    const float* x = (sel ? k : q) + (size_t)blockIdx.x * HE;
    __half* o = (sel ? g_kth : g_qth) + (size_t)blockIdx.x * HE;
    float w = dw[0];
    float p = dp[0];
    int tid = threadIdx.x;          // h*64 + e
    int e = tid & 63;
    float v = x[tid];

    __shared__ float s1[512];
    __shared__ float istd[64];
    s1[tid] = v;
    __syncthreads();
    if (tid < 64) {
        float s = 0.f, ss = 0.f;
        #pragma unroll
        for (int h = 0; h < 8; h++) {
            float u = s1[h * 64 + tid];
            s += u; ss += u * u;
        }
        float mean = s * 0.125f;
        float var = (ss - s * mean) * (1.0f / 7.0f);    // unbiased n=8
        istd[tid] = 1.0f / (sqrtf(fmaxf(var, 0.f)) + EPSF);
    }
    __syncthreads();
    o[tid] = __float2half_rn(tanhf(v * istd[e] * w) * p);
}

// ==================== kernel 1b: V -> fp16 transposed [bh][d][s] ====================
__global__ void __launch_bounds__(256) k_vconv(const float* __restrict__ V) {
    __shared__ float t[64][65];
    int bh = blockIdx.y, b = bh >> 3, h = bh & 7;
    int s0 = blockIdx.x * 64;
    const float* src = V + ((size_t)b * SS + s0) * HE + h * EE;
    int tid = threadIdx.x;
    #pragma unroll
    for (int p = 0; p < 4; p++) {
        int idx = tid + p * 256;
        int s = idx >> 4, e4 = (idx & 15) * 4;
        float4 v = *(const float4*)(src + (size_t)s * HE + e4);
        t[s][e4] = v.x; t[s][e4 + 1] = v.y; t[s][e4 + 2] = v.z; t[s][e4 + 3] = v.w;
    }
    __syncthreads();
    // store: exactly 256 items = 64 d-rows x 4 s-blocks (16 halfs each) -> ONE pass
    __half* dst = g_vt + (size_t)bh * EE * SS + s0;
    {
        int e = tid >> 2, sb = (tid & 3) * 16;
        __half2 o8[8];
        #pragma unroll
        for (int j = 0; j < 8; j++)
            o8[j] = __floats2half2_rn(t[sb + 2 * j][e], t[sb + 2 * j + 1][e]);
        *(uint4*)(dst + (size_t)e * SS + sb)     = *(uint4*)&o8[0];
        *(uint4*)(dst + (size_t)e * SS + sb + 8) = *(uint4*)&o8[4];
    }
}

// ==================== kernel 2: scores = qt @ kt^T (fp16 mma, cp.async 2-chunk) + stats ====================
#define QKPADH 40                        // halfs per tile row (80 B)
#define QKSTH (128 * QKPADH)             // halfs per stage per matrix
#define QKSMEM (4 * QKSTH * 2)           // 2 stages x (Q+K) = 40960 B

__global__ void __launch_bounds__(256, 2) k_gemm_qk() {
    extern __shared__ __half shqk[];
    __half* Qs = shqk;                   // [2][QKSTH]
    __half* Ks = shqk + 2 * QKSTH;       // [2][QKSTH]
    int bh = blockIdx.z;
    int l0 = blockIdx.y << 7, s0 = blockIdx.x << 7;
    const __half* Qh = g_qth + (size_t)(bh >> 3) * LL * HE + (bh & 7) * EE;
    const __half* Kh = g_kth + (size_t)(bh >> 3) * LL * HE + (bh & 7) * EE;
    int tid = threadIdx.x;

    int fr = tid >> 1, fc = (tid & 1) * 16;    // row, half-offset {0,16}; 2 cp.async each
    uint32_t qsb = (uint32_t)__cvta_generic_to_shared(Qs);
    uint32_t ksb = (uint32_t)__cvta_generic_to_shared(Ks);

#define ISSUEQK(kc, buf)                                                              \
    do {                                                                              \
        cpasync16(qsb + (uint32_t)((buf) * QKSTH + fr * QKPADH + fc) * 2,             \
                  Qh + (size_t)(l0 + fr) * HE + (kc) * 32 + fc);                      \
        cpasync16(qsb + (uint32_t)((buf) * QKSTH + fr * QKPADH + fc + 8) * 2,         \
                  Qh + (size_t)(l0 + fr) * HE + (kc) * 32 + fc + 8);                  \
        cpasync16(ksb + (uint32_t)((buf) * QKSTH + fr * QKPADH + fc) * 2,             \
                  Kh + (size_t)(s0 + fr) * HE + (kc) * 32 + fc);                      \
        cpasync16(ksb + (uint32_t)((buf) * QKSTH + fr * QKPADH + fc + 8) * 2,         \
                  Kh + (size_t)(s0 + fr) * HE + (kc) * 32 + fc + 8);                  \
    } while (0)

    ISSUEQK(0, 0); cp_commit();
    ISSUEQK(1, 1); cp_commit();
#undef ISSUEQK

    int lane = tid & 31, wid = tid >> 5;
    int wr = (wid >> 2) * 64;     // warp row base (2 groups)
    int wc = (wid & 3) * 32;      // warp col base (4 groups)
    int g = lane >> 2, t = lane & 3;

    float acc[4][4][4];
    #pragma unroll
    for (int i = 0; i < 4; i++)
        #pragma unroll
        for (int j = 0; j < 4; j++)
            #pragma unroll
            for (int r = 0; r < 4; r++) acc[i][j][r] = 0.f;

    #pragma unroll
    for (int kc = 0; kc < 2; kc++) {
        if (kc == 0) cp_wait<1>(); else cp_wait<0>();
        __syncthreads();
        const __half* Qb = Qs + kc * QKSTH;
        const __half* Kb = Ks + kc * QKSTH;
        #pragma unroll
        for (int k0h = 0; k0h < 32; k0h += 16) {
            uint32_t a[4][4], b[4][2];
            #pragma unroll
            for (int mi = 0; mi < 4; mi++) {
                const __half* p = Qb + (wr + mi * 16 + g) * QKPADH + k0h + 2 * t;
                a[mi][0] = *(const uint32_t*)p;
                a[mi][1] = *(const uint32_t*)(p + 8 * QKPADH);
                a[mi][2] = *(const uint32_t*)(p + 8);
                a[mi][3] = *(const uint32_t*)(p + 8 * QKPADH + 8);
            }
            #pragma unroll
            for (int ni = 0; ni < 4; ni++) {
                const __half* p = Kb + (wc + ni * 8 + g) * QKPADH + k0h + 2 * t;
                b[ni][0] = *(const uint32_t*)p;
                b[ni][1] = *(const uint32_t*)(p + 8);
            }
            #pragma unroll
            for (int mi = 0; mi < 4; mi++)
                #pragma unroll
                for (int ni = 0; ni < 4; ni++)
                    mma16(acc[mi][ni], a[mi], b[ni]);
        }
        if (kc == 0) __syncthreads();
    }

    size_t base = (size_t)bh * LL * SS;
    #pragma unroll
    for (int mi = 0; mi < 4; mi++) {
        int r0 = l0 + wr + mi * 16 + g;
        #pragma unroll
        for (int ni = 0; ni < 4; ni++) {
            int c = s0 + wc + ni * 8 + 2 * t;
            *(__half2*)&g_scores[base + (size_t)r0 * SS + c] =
                __floats2half2_rn(acc[mi][ni][0], acc[mi][ni][1]);
            *(__half2*)&g_scores[base + (size_t)(r0 + 8) * SS + c] =
                __floats2half2_rn(acc[mi][ni][2], acc[mi][ni][3]);
        }
    }

    // ---- epilogue: per-row partial (sum, sumsq) over this 128-col tile (fp32 accs) ----
    __syncthreads();                       // done with Qs/Ks; reuse smem
    float2* spart = (float2*)shqk;         // [128 rows][4 wc-groups]
    #pragma unroll
    for (int mi = 0; mi < 4; mi++) {
        float s0v = 0.f, q0v = 0.f, s1v = 0.f, q1v = 0.f;
        #pragma unroll
        for (int ni = 0; ni < 4; ni++) {
            s0v += acc[mi][ni][0] + acc[mi][ni][1];
            q0v += acc[mi][ni][0] * acc[mi][ni][0] + acc[mi][ni][1] * acc[mi][ni][1];
            s1v += acc[mi][ni][2] + acc[mi][ni][3];
            q1v += acc[mi][ni][2] * acc[mi][ni][2] + acc[mi][ni][3] * acc[mi][ni][3];
        }
        #pragma unroll
        for (int o = 1; o <= 2; o <<= 1) {
            s0v += __shfl_xor_sync(0xffffffffu, s0v, o);
            q0v += __shfl_xor_sync(0xffffffffu, q0v, o);
            s1v += __shfl_xor_sync(0xffffffffu, s1v, o);
            q1v += __shfl_xor_sync(0xffffffffu, q1v, o);
        }
        if (t == 0) {
            int rl = wr + mi * 16 + g;
            spart[rl * 4 + (wid & 3)] = make_float2(s0v, q0v);
            spart[(rl + 8) * 4 + (wid & 3)] = make_float2(s1v, q1v);
        }
    }
    __syncthreads();
    if (tid < 128) {
        float S = 0.f, Qq = 0.f;
        #pragma unroll
        for (int wcg = 0; wcg < 4; wcg++) {
            float2 v = spart[tid * 4 + wcg];
            S += v.x; Qq += v.y;
        }
        g_pstat[((size_t)bh * LL + l0 + tid) * NSTILE + blockIdx.x] = make_float2(S, Qq);
    }
}

// ==================== kernel 3: per-row alpha/shift from partials ====================
__global__ void __launch_bounds__(256) k_alpha() {
    int row = blockIdx.x * 256 + threadIdx.x;
    const float2* ps = g_pstat + (size_t)row * NSTILE;
    float S = 0.f, Q = 0.f;
    #pragma unroll
    for (int i = 0; i < NSTILE; i++) { float2 v = ps[i]; S += v.x; Q += v.y; }
    float mean = S * (1.0f / (float)SS);
    float var = (Q - S * mean) * (1.0f / (float)(SS - 1));   // unbiased
    float tau = sqrtf(fmaxf(var, 0.f) + EPSF);
    float alpha = SCALEF / tau;
    g_alsh[row] = make_float2(alpha, alpha * mean);
}

// ==================== kernel 4: out = softmax(A) @ V  (fp16 mma, 3-stage cp.async) ====================
#define APADH 40                       // halfs per A row (80 B)
#define ASTH (128 * APADH)             // halfs per A stage (10240 B)
#define VPADH 40                       // halfs per V row (transposed [d][k])
#define VSTH (64 * VPADH)              // halfs per V stage (5120 B)
#define NST 3
#define AVSMEM (NST * (ASTH + VSTH) * 2)   // 46080 B

__global__ void __launch_bounds__(256, 3) k_gemm_av(float* __restrict__ O) {
    extern __shared__ __half shav[];
    __half* Abase = shav;                    // [NST][ASTH]
    __half* Vbase = shav + NST * ASTH;       // [NST][VSTH]
    int l0 = blockIdx.x << 7;
    int bh = blockIdx.y;
    int b = bh >> 3, h = bh & 7;
    const __half* Vtr = g_vt + (size_t)bh * EE * SS;
    const __half* Ar = g_scores + (size_t)bh * LL * SS + (size_t)l0 * SS;
    int tid = threadIdx.x;

    int afr = tid >> 1, afc = (tid & 1) * 16;    // A fill: 2 cp.async per thread
    int vfr = tid >> 2, vfc = (tid & 3) * 8;     // V fill: 1 cp.async per thread
    uint32_t asb = (uint32_t)__cvta_generic_to_shared(Abase);
    uint32_t vsb = (uint32_t)__cvta_generic_to_shared(Vbase);

    int lane = tid & 31, wid = tid >> 5;
    int wr = wid * 16;               // each warp owns a unique 16-row strip, all 64 cols
    int g = lane >> 2, t4 = lane & 3;

    float2 v0 = g_alsh[(size_t)bh * LL + l0 + wr + g];
    float2 v1 = g_alsh[(size_t)bh * LL + l0 + wr + g + 8];
    float al0 = v0.x, sh0 = v0.y, al1 = v1.x, sh1 = v1.y;

    float acc[8][4];
    #pragma unroll
    for (int j = 0; j < 8; j++)
        #pragma unroll
        for (int r = 0; r < 4; r++) acc[j][r] = 0.f;
    float esum0 = 0.f, esum1 = 0.f;

#define ISSUEAV(tt, buf)                                                              \
    do {                                                                              \
        const __half* asrc = Ar + (tt) * 32;                                          \
        cpasync16(asb + (uint32_t)((buf) * ASTH + afr * APADH + afc) * 2,             \
                  asrc + (size_t)afr * SS + afc);                                     \
        cpasync16(asb + (uint32_t)((buf) * ASTH + afr * APADH + afc + 8) * 2,         \
                  asrc + (size_t)afr * SS + afc + 8);                                 \
        const __half* vsrc = Vtr + (tt) * 32;                                         \
        cpasync16(vsb + (uint32_t)((buf) * VSTH + vfr * VPADH + vfc) * 2,             \
                  vsrc + (size_t)vfr * SS + vfc);                                     \
    } while (0)

    ISSUEAV(0, 0); cp_commit();
    ISSUEAV(1, 1); cp_commit();

    for (int tt = 0; tt < 64; tt++) {
        int buf = tt % NST;
        if (tt + 2 < 64) { ISSUEAV(tt + 2, (tt + 2) % NST); cp_commit(); cp_wait<2>(); }
        else if (tt + 1 < 64) { cp_wait<1>(); }
        else { cp_wait<0>(); }
        __syncthreads();

        const __half* Ab = Abase + buf * ASTH;
        const __half* Vf = Vbase + buf * VSTH;
        #pragma unroll
        for (int k0h = 0; k0h < 32; k0h += 16) {
            uint32_t a[4];
            {
                const __half* pa = Ab + (wr + g) * APADH + k0h + 2 * t4;
                __half2 h0 = *(const __half2*)pa;                    // row g,   k..k+1
                __half2 h1 = *(const __half2*)(pa + 8 * APADH);      // row g+8
                __half2 h2 = *(const __half2*)(pa + 8);              // row g,   k+8..k+9
                __half2 h3 = *(const __half2*)(pa + 8 * APADH + 8);  // row g+8
                float2 f0 = __half22float2(h0);
                float2 f1 = __half22float2(h1);
                float2 f2 = __half22float2(h2);
                float2 f3 = __half22float2(h3);
                float e00 = __expf(fmaf(al0, f0.x, -sh0)), e01 = __expf(fmaf(al0, f0.y, -sh0));
                float e10 = __expf(fmaf(al1, f1.x, -sh1)), e11 = __expf(fmaf(al1, f1.y, -sh1));
                float e20 = __expf(fmaf(al0, f2.x, -sh0)), e21 = __expf(fmaf(al0, f2.y, -sh0));
                float e30 = __expf(fmaf(al1, f3.x, -sh1)), e31 = __expf(fmaf(al1, f3.y, -sh1));
                esum0 += e00 + e01 + e20 + e21;
                esum1 += e10 + e11 + e30 + e31;
                __half2 p0 = __floats2half2_rn(e00, e01);
                __half2 p1 = __floats2half2_rn(e10, e11);
                __half2 p2 = __floats2half2_rn(e20, e21);
                __half2 p3 = __floats2half2_rn(e30, e31);
                a[0] = h2u(p0); a[1] = h2u(p1); a[2] = h2u(p2); a[3] = h2u(p3);
            }
            #pragma unroll
            for (int ni = 0; ni < 8; ni++) {
                const __half* pv = Vf + (ni * 8 + g) * VPADH + k0h + 2 * t4;
                uint32_t bf[2];
                bf[0] = *(const uint32_t*)pv;
                bf[1] = *(const uint32_t*)(pv + 8);
                mma16(acc[ni], a, bf);
            }
        }
        __syncthreads();
    }
#undef ISSUEAV

    // expsum: butterfly over the t4 quad -> every lane holds the row total
    esum0 += __shfl_xor_sync(0xffffffffu, esum0, 1);
    esum0 += __shfl_xor_sync(0xffffffffu, esum0, 2);
    esum1 += __shfl_xor_sync(0xffffffffu, esum1, 1);
    esum1 += __shfl_xor_sync(0xffffffffu, esum1, 2);
    float inv0 = 1.0f / esum0;
    float inv1 = 1.0f / esum1;

    int r0 = l0 + wr + g;
    #pragma unroll
    for (int ni = 0; ni < 8; ni++) {
        int d = ni * 8 + 2 * t4;
        size_t o0 = ((size_t)((size_t)b * LL + r0) * HH + h) * EE + d;
        *(float2*)&O[o0] = make_float2(acc[ni][0] * inv0, acc[ni][1] * inv0);
        size_t o1 = ((size_t)((size_t)b * LL + r0 + 8) * HH + h) * EE + d;
        *(float2*)&O[o1] = make_float2(acc[ni][2] * inv1, acc[ni][3] * inv1);
    }
}

// ==================== launch ====================
extern "C" void kernel_launch(void* const* d_in, const int* in_sizes, int n_in,
                              void* d_out, int out_size) {
    const float* q  = (const float*)d_in[0];
    const float* k  = (const float*)d_in[1];
    const float* v  = (const float*)d_in[2];
    const float* dw = (const float*)d_in[4];
    const float* dp = (const float*)d_in[5];
    float* out = (float*)d_out;

    cudaFuncSetAttribute(k_gemm_qk, cudaFuncAttributeMaxDynamicSharedMemorySize, QKSMEM);
    cudaFuncSetAttribute(k_gemm_av, cudaFuncAttributeMaxDynamicSharedMemorySize, AVSMEM);

    k_transform<<<dim3(BB * LL, 2), 512>>>(q, k, dw, dp);
    k_vconv    <<<dim3(SS / 64, BH), 256>>>(v);
    k_gemm_qk  <<<dim3(SS / 128, LL / 128, BH), 256, QKSMEM>>>();
    k_alpha    <<<NROWS / 256, 256>>>();
    k_gemm_av  <<<dim3(LL / 128, BH), 256, AVSMEM>>>(out);
}

// round 15
// speedup vs baseline: 6.3059x; 1.2005x over previous
#include <cuda_runtime.h>
#include <cuda_fp16.h>
#include <math.h>
#include <stdint.h>

#define BB 4
#define LL 2048
#define SS 2048
#define HH 8
#define EE 64
#define HE 512          // HH*EE
#define BH 32           // BB*HH
#define NELEM (BB*LL*HH*EE)
#define NROWS (BH * LL)      // 65536 attention rows
#define EPSF 1e-6f
#define SCALEF 0.125f   // 1/sqrt(64)
#define NSP 8           // gram s-partitions

// -------- device scratch (alloc-free rule: __device__ globals) --------
__device__ __half g_qth[NELEM];                    // fp16 transformed Q (8 MB)
__device__ __half g_kth[NELEM];                    // fp16 transformed K
__device__ __half g_vt[(size_t)BH * EE * SS];      // fp16 V transposed [bh][d][s] (8 MB)
__device__ float  g_gramp[(size_t)BH * NSP * 64 * 64]; // partial Gram (4 MB)
__device__ float  g_ksump[(size_t)BH * NSP * 64];
__device__ float2 g_alsh[NROWS];                   // per row: (alpha, shift)

__device__ __forceinline__ void mma16(float* c, const uint32_t* a, const uint32_t* b) {
    asm volatile("mma.sync.aligned.m16n8k16.row.col.f32.f16.f16.f32 "
                 "{%0,%1,%2,%3},{%4,%5,%6,%7},{%8,%9},{%0,%1,%2,%3};"
                 : "+f"(c[0]), "+f"(c[1]), "+f"(c[2]), "+f"(c[3])
                 : "r"(a[0]), "r"(a[1]), "r"(a[2]), "r"(a[3]), "r"(b[0]), "r"(b[1]));
}

__device__ __forceinline__ void cpasync16(uint32_t dst, const void* src) {
    asm volatile("cp.async.cg.shared.global [%0], [%1], 16;" :: "r"(dst), "l"(src));
}
__device__ __forceinline__ void cp_commit() { asm volatile("cp.async.commit_group;"); }
template<int N> __device__ __forceinline__ void cp_wait() {
    asm volatile("cp.async.wait_group %0;" :: "n"(N));
}
__device__ __forceinline__ uint32_t h2u(__half2 h) { return *reinterpret_cast<uint32_t*>(&h); }

// ==================== kernel 1: transform; std over HEADS (axis=-2), fp16 out ====================
__global__ void __launch_bounds__(512) k_transform(const float* __restrict__ q,
                                                   const float* __restrict__ k,
                                                   const float* __restrict__ dw,
                                                   const float* __restrict__ dp) {
    int sel = blockIdx.y;
    const float* x = (sel ? k : q) + (size_t)blockIdx.x * HE;
    __half* o = (sel ? g_kth : g_qth) + (size_t)blockIdx.x * HE;
    float w = dw[0];
    float p = dp[0];
    int tid = threadIdx.x;          // h*64 + e
    int e = tid & 63;
    float v = x[tid];

    __shared__ float s1[512];
    __shared__ float istd[64];
    s1[tid] = v;
    __syncthreads();
    if (tid < 64) {
        float s = 0.f, ss = 0.f;
        #pragma unroll
        for (int h = 0; h < 8; h++) {
            float u = s1[h * 64 + tid];
            s += u; ss += u * u;
        }
        float mean = s * 0.125f;
        float var = (ss - s * mean) * (1.0f / 7.0f);    // unbiased n=8
        istd[tid] = 1.0f / (sqrtf(fmaxf(var, 0.f)) + EPSF);
    }
    __syncthreads();
    o[tid] = __float2half_rn(tanhf(v * istd[e] * w) * p);
}

// ==================== kernel 1b: V -> fp16 transposed [bh][d][s] ====================
__global__ void __launch_bounds__(256) k_vconv(const float* __restrict__ V) {
    __shared__ float t[64][65];
    int bh = blockIdx.y, b = bh >> 3, h = bh & 7;
    int s0 = blockIdx.x * 64;
    const float* src = V + ((size_t)b * SS + s0) * HE + h * EE;
    int tid = threadIdx.x;
    #pragma unroll
    for (int p = 0; p < 4; p++) {
        int idx = tid + p * 256;
        int s = idx >> 4, e4 = (idx & 15) * 4;
        float4 v = *(const float4*)(src + (size_t)s * HE + e4);
        t[s][e4] = v.x; t[s][e4 + 1] = v.y; t[s][e4 + 2] = v.z; t[s][e4 + 3] = v.w;
    }
    __syncthreads();
    __half* dst = g_vt + (size_t)bh * EE * SS + s0;
    {
        int e = tid >> 2, sb = (tid & 3) * 16;
        __half2 o8[8];
        #pragma unroll
        for (int j = 0; j < 8; j++)
            o8[j] = __floats2half2_rn(t[sb + 2 * j][e], t[sb + 2 * j + 1][e]);
        *(uint4*)(dst + (size_t)e * SS + sb)     = *(uint4*)&o8[0];
        *(uint4*)(dst + (size_t)e * SS + sb + 8) = *(uint4*)&o8[4];
    }
}

// ==================== kernel 2: partial Gram G = K^T K and ksum, per (bh, s-slice) ====================
__global__ void __launch_bounds__(256) k_gram() {
    __shared__ float tile[32][64];
    int sp = blockIdx.x, bh = blockIdx.y;
    int b = bh >> 3, h = bh & 7;
    const __half* K = g_kth + (size_t)b * LL * HE + h * EE;
    int tid = threadIdx.x;
    int e = tid >> 2, fb = (tid & 3) * 16;
    int lr = tid >> 3, lc = (tid & 7) * 8;

    float gacc[16] = {};
    float ksacc = 0.f;
    for (int blk = 0; blk < 8; blk++) {
        int s0 = sp * 256 + blk * 32;
        {   // load 32 rows x 64 halfs, converted to float
            uint4 raw = *(const uint4*)(K + (size_t)(s0 + lr) * HE + lc);
            __half2* hp = (__half2*)&raw;
            #pragma unroll
            for (int j = 0; j < 4; j++) {
                float2 f = __half22float2(hp[j]);
                tile[lr][lc + 2 * j] = f.x;
                tile[lr][lc + 2 * j + 1] = f.y;
            }
        }
        __syncthreads();
        for (int s = 0; s < 32; s++) {
            float ke = tile[s][e];
            if ((tid & 3) == 0) ksacc += ke;
            #pragma unroll
            for (int j = 0; j < 16; j++)
                gacc[j] += ke * tile[s][fb + j];
        }
        __syncthreads();
    }
    float* gp = g_gramp + ((size_t)bh * NSP + sp) * 4096;
    #pragma unroll
    for (int j = 0; j < 16; j++)
        gp[e * 64 + fb + j] = gacc[j];
    if ((tid & 3) == 0)
        g_ksump[((size_t)bh * NSP + sp) * 64 + e] = ksacc;
}

// ==================== kernel 3: per-row alpha/shift from Gram: s2 = q^T G q, s1 = q . ksum ====================
__global__ void __launch_bounds__(256) k_alpha2() {
    __shared__ float sG[4096];
    __shared__ float sks[64];
    int bh = blockIdx.x >> 3;
    int l0 = (blockIdx.x & 7) * 256;
    int b = bh >> 3, h = bh & 7;
    int tid = threadIdx.x;

    #pragma unroll
    for (int j = 0; j < 16; j++) {
        int idx = j * 256 + tid;
        float a = 0.f;
        #pragma unroll
        for (int p = 0; p < NSP; p++)
            a += g_gramp[((size_t)bh * NSP + p) * 4096 + idx];
        sG[idx] = a;
    }
    if (tid < 64) {
        float a = 0.f;
        #pragma unroll
        for (int p = 0; p < NSP; p++)
            a += g_ksump[((size_t)bh * NSP + p) * 64 + tid];
        sks[tid] = a;
    }
    __syncthreads();

    int l = l0 + tid;
    const __half* qr = g_qth + ((size_t)(b * LL + l) * HH + h) * EE;
    uint4 qraw[8];
    #pragma unroll
    for (int j = 0; j < 8; j++) qraw[j] = *(const uint4*)(qr + j * 8);
    const __half2* qh = (const __half2*)qraw;   // 32 half2

    float s1 = 0.f, s2 = 0.f;
    #pragma unroll 4
    for (int e = 0; e < 64; e++) {
        float2 qe2 = __half22float2(qh[e >> 1]);
        float qe = (e & 1) ? qe2.y : qe2.x;
        s1 += qe * sks[e];
        const float* Ge = sG + e * 64;
        float t = 0.f;
        #pragma unroll
        for (int f2 = 0; f2 < 32; f2++) {
            float2 qf = __half22float2(qh[f2]);
            t += Ge[2 * f2] * qf.x + Ge[2 * f2 + 1] * qf.y;
        }
        s2 += qe * t;
    }
    float mean = s1 * (1.0f / (float)SS);
    float var = (s2 - s1 * mean) * (1.0f / (float)(SS - 1));   // unbiased
    float tau = sqrtf(fmaxf(var, 0.f) + EPSF);
    float alpha = SCALEF / tau;
    g_alsh[(size_t)bh * LL + l] = make_float2(alpha, alpha * mean);
}

// ==================== kernel 4: fused flash: out = softmax_tau(Q K^T) V ====================
#define QPADH 72                       // halfs per Q/K row (144 B, 16B-aligned, conflict-free)
#define QTILE (128 * QPADH)            // 9216 halfs
#define KST (32 * QPADH)               // 2304 halfs per K stage
#define VPADH 40
#define VST (64 * VPADH)               // 2560 halfs per V stage
#define FNST 3
#define FSMEM ((QTILE + FNST * (KST + VST)) * 2)   // 47616 B

__global__ void __launch_bounds__(256, 2) k_flash(float* __restrict__ O) {
    extern __shared__ __half sh[];
    __half* Qs  = sh;                         // [128][QPADH]
    __half* Ksb = sh + QTILE;                 // [FNST][32][QPADH]
    __half* Vsb = sh + QTILE + FNST * KST;    // [FNST][64][VPADH]
    int l0 = blockIdx.x << 7;
    int bh = blockIdx.y;
    int b = bh >> 3, h = bh & 7;
    const __half* Qg = g_qth + ((size_t)(b * LL + l0)) * HE + h * EE;
    const __half* Kg = g_kth + (size_t)b * LL * HE + h * EE;
    const __half* Vt = g_vt + (size_t)bh * EE * SS;
    int tid = threadIdx.x;

    uint32_t qsb = (uint32_t)__cvta_generic_to_shared(Qs);
    uint32_t ksb = (uint32_t)__cvta_generic_to_shared(Ksb);
    uint32_t vsb = (uint32_t)__cvta_generic_to_shared(Vsb);

    // ---- issue Q tile (128 rows x 64 halfs): 2 threads/row, 4x16B each ----
    {
        int qr = tid >> 1, qc = (tid & 1) * 32;
        #pragma unroll
        for (int j = 0; j < 4; j++)
            cpasync16(qsb + (uint32_t)(qr * QPADH + qc + j * 8) * 2,
                      Qg + (size_t)qr * HE + qc + j * 8);
        cp_commit();
    }

    int kfr = tid >> 3, kfc = (tid & 7) * 8;   // K fill: 32 rows x 64 halfs
    int vfr = tid >> 2, vfc = (tid & 3) * 8;   // V fill: 64 rows x 32 halfs

#define ISSUEF(tt, buf)                                                               \
    do {                                                                              \
        cpasync16(ksb + (uint32_t)((buf) * KST + kfr * QPADH + kfc) * 2,              \
                  Kg + (size_t)((tt) * 32 + kfr) * HE + kfc);                         \
        cpasync16(vsb + (uint32_t)((buf) * VST + vfr * VPADH + vfc) * 2,              \
                  Vt + (size_t)vfr * SS + (tt) * 32 + vfc);                           \
    } while (0)

    ISSUEF(0, 0); cp_commit();
    ISSUEF(1, 1); cp_commit();

    int lane = tid & 31, wid = tid >> 5;
    int wr = wid * 16;
    int g = lane >> 2, t4 = lane & 3;

    float2 v0 = g_alsh[(size_t)bh * LL + l0 + wr + g];
    float2 v1 = g_alsh[(size_t)bh * LL + l0 + wr + g + 8];
    float al0 = v0.x, sh0 = v0.y, al1 = v1.x, sh1 = v1.y;

    // ---- Q fragments to registers (after Q group drains) ----
    cp_wait<2>();      // Q group done; stages 0,1 may be in flight
    __syncthreads();
    uint32_t qa[4][4];
    #pragma unroll
    for (int ks = 0; ks < 4; ks++) {
        const __half* p = Qs + (wr + g) * QPADH + ks * 16 + 2 * t4;
        qa[ks][0] = *(const uint32_t*)p;
        qa[ks][1] = *(const uint32_t*)(p + 8 * QPADH);
        qa[ks][2] = *(const uint32_t*)(p + 8);
        qa[ks][3] = *(const uint32_t*)(p + 8 * QPADH + 8);
    }

    float acc[8][4];
    #pragma unroll
    for (int j = 0; j < 8; j++)
        #pragma unroll
        for (int r = 0; r < 4; r++) acc[j][r] = 0.f;
    float esum0 = 0.f, esum1 = 0.f;

    for (int tt = 0; tt < 64; tt++) {
        int buf = tt % FNST;
        if (tt + 2 < 64) { ISSUEF(tt + 2, (tt + 2) % FNST); cp_commit(); cp_wait<2>(); }
        else if (tt + 1 < 64) { cp_wait<1>(); }
        else { cp_wait<0>(); }
        __syncthreads();

        const __half* Kb = Ksb + buf * KST;
        const __half* Vf = Vsb + buf * VST;

        // MMA1: S = Q K^T for this 32-s chunk (4 n-tiles x 4 k-steps)
        float sacc[4][4];
        #pragma unroll
        for (int ni = 0; ni < 4; ni++)
            #pragma unroll
            for (int r = 0; r < 4; r++) sacc[ni][r] = 0.f;
        #pragma unroll
        for (int ks = 0; ks < 4; ks++) {
            #pragma unroll
            for (int ni = 0; ni < 4; ni++) {
                const __half* p = Kb + (ni * 8 + g) * QPADH + ks * 16 + 2 * t4;
                uint32_t bf[2];
                bf[0] = *(const uint32_t*)p;
                bf[1] = *(const uint32_t*)(p + 8);
                mma16(sacc[ni], qa[ks], bf);
            }
        }

        // exp on accumulators + pack into MMA2 A-fragments
        uint32_t pa[2][4];
        #pragma unroll
        for (int ni = 0; ni < 4; ni++) {
            float e0 = __expf(fmaf(al0, sacc[ni][0], -sh0));
            float e1 = __expf(fmaf(al0, sacc[ni][1], -sh0));
            float e2 = __expf(fmaf(al1, sacc[ni][2], -sh1));
            float e3 = __expf(fmaf(al1, sacc[ni][3], -sh1));
            esum0 += e0 + e1;
            esum1 += e2 + e3;
            uint32_t lo = h2u(__floats2half2_rn(e0, e1));
            uint32_t hi = h2u(__floats2half2_rn(e2, e3));
            pa[ni >> 1][(ni & 1) * 2]     = lo;   // a0 (ni even) / a2 (ni odd)
            pa[ni >> 1][(ni & 1) * 2 + 1] = hi;   // a1 / a3
        }

        // MMA2: out += P V (2 k-steps x 8 d-tiles)
        #pragma unroll
        for (int kk = 0; kk < 2; kk++) {
            #pragma unroll
            for (int nj = 0; nj < 8; nj++) {
                const __half* pv = Vf + (nj * 8 + g) * VPADH + kk * 16 + 2 * t4;
                uint32_t bf[2];
                bf[0] = *(const uint32_t*)pv;
                bf[1] = *(const uint32_t*)(pv + 8);
                mma16(acc[nj], pa[kk], bf);
            }
        }
        __syncthreads();
    }
#undef ISSUEF

    // expsum quad-butterfly
    esum0 += __shfl_xor_sync(0xffffffffu, esum0, 1);
    esum0 += __shfl_xor_sync(0xffffffffu, esum0, 2);
    esum1 += __shfl_xor_sync(0xffffffffu, esum1, 1);
    esum1 += __shfl_xor_sync(0xffffffffu, esum1, 2);
    float inv0 = 1.0f / esum0;
    float inv1 = 1.0f / esum1;

    int r0 = l0 + wr + g;
    #pragma unroll
    for (int nj = 0; nj < 8; nj++) {
        int d = nj * 8 + 2 * t4;
        size_t o0 = ((size_t)((size_t)b * LL + r0) * HH + h) * EE + d;
        *(float2*)&O[o0] = make_float2(acc[nj][0] * inv0, acc[nj][1] * inv0);
        size_t o1 = ((size_t)((size_t)b * LL + r0 + 8) * HH + h) * EE + d;
        *(float2*)&O[o1] = make_float2(acc[nj][2] * inv1, acc[nj][3] * inv1);
    }
}

// ==================== launch ====================
extern "C" void kernel_launch(void* const* d_in, const int* in_sizes, int n_in,
                              void* d_out, int out_size) {
    const float* q  = (const float*)d_in[0];
    const float* k  = (const float*)d_in[1];
    const float* v  = (const float*)d_in[2];
    const float* dw = (const float*)d_in[4];
    const float* dp = (const float*)d_in[5];
    float* out = (float*)d_out;

    cudaFuncSetAttribute(k_flash, cudaFuncAttributeMaxDynamicSharedMemorySize, FSMEM);

    k_transform<<<dim3(BB * LL, 2), 512>>>(q, k, dw, dp);
    k_vconv    <<<dim3(SS / 64, BH), 256>>>(v);
    k_gram     <<<dim3(NSP, BH), 256>>>();
    k_alpha2   <<<NROWS / 256, 256>>>();
    k_flash    <<<dim3(LL / 128, BH), 256, FSMEM>>>(out);
}